// round 11
// baseline (speedup 1.0000x reference)
#include <cuda_runtime.h>
#include <math_constants.h>
#include <cstdint>

#define SQ 2048
#define NB 4
#define ND 256
#define NE 256
#define NH 8
#define HD 32
#define MROWS (SQ*NB)       // 8192
#define LDQKV (3*NE)        // 768

// ---------------- scratch (device globals; no allocation) ----------------
__device__ __align__(16) float g_Weff[3*NE*ND];
__device__ __align__(16) float g_beff[3*NE];
__device__ __align__(16) float g_Wcomb[ND*NE];
__device__ __align__(16) float g_bcomb[ND];
__device__ __align__(16) float g_qkv[(size_t)MROWS*LDQKV];
__device__ __align__(16) float g_ctx[(size_t)MROWS*NE];
__device__ __align__(16) float g_y[(size_t)MROWS*ND];

extern __shared__ float sdyn[];

// ---------------- helpers ----------------
__device__ __forceinline__ void mma_tf32(float c[4],
                                         uint32_t a0, uint32_t a1, uint32_t a2, uint32_t a3,
                                         uint32_t b0, uint32_t b1)
{
    asm volatile("mma.sync.aligned.m16n8k8.row.col.f32.tf32.tf32.f32 "
                 "{%0,%1,%2,%3}, {%4,%5,%6,%7}, {%8,%9}, {%0,%1,%2,%3};"
                 : "+f"(c[0]), "+f"(c[1]), "+f"(c[2]), "+f"(c[3])
                 : "r"(a0), "r"(a1), "r"(a2), "r"(a3), "r"(b0), "r"(b1));
}

__device__ __forceinline__ void cp16(void* smem_dst, const void* gmem_src) {
    uint32_t sa = (uint32_t)__cvta_generic_to_shared(smem_dst);
    asm volatile("cp.async.cg.shared.global [%0], [%1], 16;\n" :: "r"(sa), "l"(gmem_src));
}

// ---------------- prep: 4 small 256^3 products + bias folds ----------------
__global__ void prep_gemmAB(const float* __restrict__ Win,
                            const float* __restrict__ Wq, const float* __restrict__ Wk,
                            const float* __restrict__ Wv, const float* __restrict__ Wfc,
                            const float* __restrict__ Wout,
                            const float* __restrict__ bin_, const float* __restrict__ bq,
                            const float* __restrict__ bk, const float* __restrict__ bv,
                            const float* __restrict__ bout, const float* __restrict__ bfc)
{
    const int t = threadIdx.x;
    if (blockIdx.z == 4) {
        int xb = blockIdx.y * 4 + blockIdx.x;      // 0..15
        int warp = t >> 5, lane = t & 31;
        #pragma unroll
        for (int o = 0; o < 8; o++) {
            int wid = xb * 64 + warp * 8 + o;      // 0..1023
            const float* row; const float* vec; float base;
            if (wid < 3*NE) {
                int tt = wid >> 8;
                row = Win + (size_t)wid * NE;
                vec = (tt == 0) ? bq : (tt == 1) ? bk : bv;
                base = bin_[wid];
            } else {
                int r = wid - 3*NE;
                row = Wfc + (size_t)r * NE;
                vec = bout;
                base = bfc[r];
            }
            float s = 0.f;
            #pragma unroll
            for (int u = 0; u < 8; u++) s += row[u*32 + lane] * vec[u*32 + lane];
            #pragma unroll
            for (int off = 16; off >= 1; off >>= 1) s += __shfl_xor_sync(0xffffffffu, s, off);
            if (lane == 0) {
                if (wid < 3*NE) g_beff[wid] = base + s;
                else            g_bcomb[wid - 3*NE] = base + s;
            }
        }
        return;
    }

    __shared__ __align__(16) float As[16][68];   // [c][r]
    __shared__ __align__(16) float Bs[16][68];   // [c][d]
    const int tt = blockIdx.z;
    const float* A; const float* B; float* C;
    if (tt < 3) { A = Win + (size_t)tt*NE*NE; B = (tt==0)?Wq:(tt==1)?Wk:Wv; C = g_Weff + (size_t)tt*NE*ND; }
    else        { A = Wfc; B = Wout; C = g_Wcomb; }

    const int m0  = blockIdx.y * 64;
    const int d0  = blockIdx.x * 64;
    const int lrow = t >> 2;
    const int lc4  = (t & 3) << 2;
    const int brow = t >> 4;
    const int bc4  = (t & 15) << 2;
    const int ty = t >> 4, tx = t & 15;

    float acc[4][4] = {};
    for (int k0 = 0; k0 < NE; k0 += 16) {
        float4 av = *(const float4*)&A[(size_t)(m0 + lrow)*NE + k0 + lc4];
        As[lc4+0][lrow] = av.x; As[lc4+1][lrow] = av.y;
        As[lc4+2][lrow] = av.z; As[lc4+3][lrow] = av.w;
        *(float4*)&Bs[brow][bc4] = *(const float4*)&B[(size_t)(k0 + brow)*NE + d0 + bc4];
        __syncthreads();
        #pragma unroll
        for (int kk = 0; kk < 16; kk++) {
            float4 a4 = *(const float4*)&As[kk][ty << 2];
            float4 b4 = *(const float4*)&Bs[kk][tx << 2];
            float ar[4] = {a4.x, a4.y, a4.z, a4.w};
            float br[4] = {b4.x, b4.y, b4.z, b4.w};
            #pragma unroll
            for (int i = 0; i < 4; i++)
                #pragma unroll
                for (int j = 0; j < 4; j++)
                    acc[i][j] += ar[i] * br[j];
        }
        __syncthreads();
    }
    #pragma unroll
    for (int i = 0; i < 4; i++) {
        float4 o = {acc[i][0], acc[i][1], acc[i][2], acc[i][3]};
        *(float4*)&C[(size_t)(m0 + (ty<<2) + i)*NE + d0 + (tx<<2)] = o;
    }
}

// ---------------- tensor-core GEMM, 3-stage cp.async pipeline, BK=16 ----------------
// C[M,N] = A[M,K] @ W[N,K]^T + bias (+resid). Block tile 128x128, BK=16,
// 256 threads, warp tile 64x32. One __syncthreads per K-tile.
// Stage = 128x20 floats per matrix -> 61440 B total -> 2 blocks/SM.
#define GST 20
#define GSTAGE (128*GST)
#define GEMM_SMEM (6*GSTAGE*(int)sizeof(float))   // 61440 B
__global__ void __launch_bounds__(256, 2) gemm_mma(const float* __restrict__ A,
                                                   const float* __restrict__ W,
                                                   const float* __restrict__ bias,
                                                   const float* __restrict__ resid,
                                                   float* __restrict__ C, int N, int K)
{
    const int tid = threadIdx.x;
    const int m0 = blockIdx.y * 128;
    const int n0 = blockIdx.x * 128;
    const int warp = tid >> 5;
    const int lane = tid & 31;
    const int wm = warp >> 2;
    const int wn = warp & 3;
    const int grp = lane >> 2;
    const int tig = lane & 3;
    const int ldr = tid >> 2;           // 0..63
    const int ldc = (tid & 3) << 2;     // 0,4,8,12

    const int T = K >> 4;
    float acc[4][4][4] = {};

    // prefetch stages 0,1
    #pragma unroll
    for (int s = 0; s < 2; s++) {
        float* As = sdyn + s*2*GSTAGE;
        float* Bs = As + GSTAGE;
        int k0 = s << 4;
        #pragma unroll
        for (int p = 0; p < 2; p++) {
            int row = ldr + p * 64;
            cp16(&As[row*GST + ldc], &A[(size_t)(m0 + row)*K + k0 + ldc]);
            cp16(&Bs[row*GST + ldc], &W[(size_t)(n0 + row)*K + k0 + ldc]);
        }
        asm volatile("cp.async.commit_group;\n");
    }

    for (int t = 0; t < T; t++) {
        if (t + 1 < T) asm volatile("cp.async.wait_group 1;\n");
        else           asm volatile("cp.async.wait_group 0;\n");
        __syncthreads();

        if (t + 2 < T) {
            int s = (t + 2) % 3;
            int k0 = (t + 2) << 4;
            float* As = sdyn + s*2*GSTAGE;
            float* Bs = As + GSTAGE;
            #pragma unroll
            for (int p = 0; p < 2; p++) {
                int row = ldr + p * 64;
                cp16(&As[row*GST + ldc], &A[(size_t)(m0 + row)*K + k0 + ldc]);
                cp16(&Bs[row*GST + ldc], &W[(size_t)(n0 + row)*K + k0 + ldc]);
            }
            asm volatile("cp.async.commit_group;\n");
        }

        const float* As = sdyn + (t % 3)*2*GSTAGE;
        const float* Bs = As + GSTAGE;
        #pragma unroll
        for (int kk = 0; kk < 16; kk += 8) {
            uint32_t af[4][4], bf[4][2];
            #pragma unroll
            for (int mt = 0; mt < 4; mt++) {
                int r = (wm*64 + mt*16 + grp) * GST;
                af[mt][0] = __float_as_uint(As[r + kk + tig]);
                af[mt][1] = __float_as_uint(As[r + 8*GST + kk + tig]);
                af[mt][2] = __float_as_uint(As[r + kk + 4 + tig]);
                af[mt][3] = __float_as_uint(As[r + 8*GST + kk + 4 + tig]);
            }
            #pragma unroll
            for (int nt = 0; nt < 4; nt++) {
                int c = (wn*32 + nt*8 + grp) * GST;
                bf[nt][0] = __float_as_uint(Bs[c + kk + tig]);
                bf[nt][1] = __float_as_uint(Bs[c + kk + 4 + tig]);
            }
            #pragma unroll
            for (int mt = 0; mt < 4; mt++)
                #pragma unroll
                for (int nt = 0; nt < 4; nt++)
                    mma_tf32(acc[mt][nt], af[mt][0], af[mt][1], af[mt][2], af[mt][3],
                             bf[nt][0], bf[nt][1]);
        }
    }

    #pragma unroll
    for (int mt = 0; mt < 4; mt++) {
        #pragma unroll
        for (int nt = 0; nt < 4; nt++) {
            int col = n0 + wn*32 + nt*8 + 2*tig;
            float bx = bias[col], by = bias[col + 1];
            int r0 = m0 + wm*64 + mt*16 + grp;
            float2 o0 = {acc[mt][nt][0] + bx, acc[mt][nt][1] + by};
            float2 o1 = {acc[mt][nt][2] + bx, acc[mt][nt][3] + by};
            if (resid) {
                float2 r0v = *(const float2*)&resid[(size_t)r0 * N + col];
                float2 r1v = *(const float2*)&resid[(size_t)(r0 + 8) * N + col];
                o0.x += r0v.x; o0.y += r0v.y;
                o1.x += r1v.x; o1.y += r1v.y;
            }
            *(float2*)&C[(size_t)r0 * N + col] = o0;
            *(float2*)&C[(size_t)(r0 + 8) * N + col] = o1;
        }
    }
}

// ---------------- banded attention via tensor cores ----------------
// Block: 128 queries x one (b,h), 256 threads (8 warps), warp owns 16 queries.
#define KST 36     // sK row stride
#define VST 180    // sVT row stride (mod 32 = 20, conflict-free frag reads)
#define QST 36     // sQ row stride
#define PST 68     // sP row stride
#define KROWS 176
#define SK_F   (KROWS*KST)           // 6336
#define SVT_F  (32*VST)              // 5760
#define SU_F   (8*16*PST)            // 8704 (>= 128*QST = 4608)
#define ATTN_SMEM ((SK_F + SVT_F + SU_F)*(int)sizeof(float))   // 83200 B
__global__ void __launch_bounds__(256) attn_mma(const int* __restrict__ reqp,
                                                float* __restrict__ ctx)
{
    float* sK  = sdyn;
    float* sVT = sdyn + SK_F;
    float* sU  = sdyn + SK_F + SVT_F;

    const float* qkv = g_qkv;
    const int req = *reqp;
    const int bh = blockIdx.y;
    const int b = bh >> 3;
    const int hoff = (bh & 7) * HD;
    const int q0 = blockIdx.x * 128;
    const int wbase = q0 - (req - 1);

    const int tid = threadIdx.x;
    const int w = tid >> 5;
    const int lane = tid & 31;
    const int grp = lane >> 2;
    const int tig = lane & 3;
    const float scale = rsqrtf((float)HD);

    #pragma unroll
    for (int u = tid; u < 128*8; u += 256) {         // Q: 128 rows x 8 float4
        int r = u >> 3, c4 = (u & 7) << 2;
        float4 v = *(const float4*)&qkv[(size_t)((q0 + r)*NB + b)*LDQKV + hoff + c4];
        sU[r*QST + c4 + 0] = v.x * scale;
        sU[r*QST + c4 + 1] = v.y * scale;
        sU[r*QST + c4 + 2] = v.z * scale;
        sU[r*QST + c4 + 3] = v.w * scale;
    }
    for (int u = tid; u < KROWS*8; u += 256) {       // K + V: 176 rows x 8 float4
        int r = u >> 3, c4 = (u & 7) << 2;
        int key = wbase + r;
        float4 kv = {0.f, 0.f, 0.f, 0.f}, vv = {0.f, 0.f, 0.f, 0.f};
        if (key >= 0 && key < SQ) {
            size_t base = (size_t)(key*NB + b)*LDQKV + hoff + c4;
            kv = *(const float4*)&qkv[base + NE];
            vv = *(const float4*)&qkv[base + 2*NE];
        }
        sK[r*KST + c4 + 0] = kv.x;
        sK[r*KST + c4 + 1] = kv.y;
        sK[r*KST + c4 + 2] = kv.z;
        sK[r*KST + c4 + 3] = kv.w;
        sVT[(c4+0)*VST + r] = vv.x;
        sVT[(c4+1)*VST + r] = vv.y;
        sVT[(c4+2)*VST + r] = vv.z;
        sVT[(c4+3)*VST + r] = vv.w;
    }
    __syncthreads();

    // ---- scores: S[16x64] = Q @ K^T ----
    float sc[8][4] = {};
    #pragma unroll
    for (int ks = 0; ks < 4; ks++) {
        int kk = ks * 8;
        uint32_t af[4], bf[8][2];
        {
            int r = (w*16 + grp) * QST;
            af[0] = __float_as_uint(sU[r + kk + tig]);
            af[1] = __float_as_uint(sU[r + 8*QST + kk + tig]);
            af[2] = __float_as_uint(sU[r + kk + 4 + tig]);
            af[3] = __float_as_uint(sU[r + 8*QST + kk + 4 + tig]);
        }
        #pragma unroll
        for (int nt = 0; nt < 8; nt++) {
            int r = (w*16 + nt*8 + grp) * KST;
            bf[nt][0] = __float_as_uint(sK[r + kk + tig]);
            bf[nt][1] = __float_as_uint(sK[r + kk + 4 + tig]);
        }
        #pragma unroll
        for (int nt = 0; nt < 8; nt++)
            mma_tf32(sc[nt], af[0], af[1], af[2], af[3], bf[nt][0], bf[nt][1]);
    }

    // ---- mask + softmax (registers) ----
    const int iw = q0 + w*16;
    const int jw = wbase + w*16;
    float mx0 = -CUDART_INF_F, mx1 = -CUDART_INF_F;
    {
        int i0 = iw + grp, i1 = i0 + 8;
        #pragma unroll
        for (int nt = 0; nt < 8; nt++) {
            int j0 = jw + nt*8 + 2*tig;
            int j1 = j0 + 1;
            bool g0 = (j0 >= 0) & (j0 < SQ);
            bool g1 = (j1 >= 0) & (j1 < SQ);
            float* c = sc[nt];
            c[0] = (g0 && abs(i0 - j0) < req) ? c[0] : -CUDART_INF_F;
            c[1] = (g1 && abs(i0 - j1) < req) ? c[1] : -CUDART_INF_F;
            c[2] = (g0 && abs(i1 - j0) < req) ? c[2] : -CUDART_INF_F;
            c[3] = (g1 && abs(i1 - j1) < req) ? c[3] : -CUDART_INF_F;
            mx0 = fmaxf(mx0, fmaxf(c[0], c[1]));
            mx1 = fmaxf(mx1, fmaxf(c[2], c[3]));
        }
    }
    #pragma unroll
    for (int o = 1; o <= 2; o <<= 1) {
        mx0 = fmaxf(mx0, __shfl_xor_sync(0xffffffffu, mx0, o));
        mx1 = fmaxf(mx1, __shfl_xor_sync(0xffffffffu, mx1, o));
    }
    float s0 = 0.f, s1 = 0.f;
    #pragma unroll
    for (int nt = 0; nt < 8; nt++) {
        float* c = sc[nt];
        c[0] = __expf(c[0] - mx0);
        c[1] = __expf(c[1] - mx0);
        c[2] = __expf(c[2] - mx1);
        c[3] = __expf(c[3] - mx1);
        s0 += c[0] + c[1];
        s1 += c[2] + c[3];
    }
    #pragma unroll
    for (int o = 1; o <= 2; o <<= 1) {
        s0 += __shfl_xor_sync(0xffffffffu, s0, o);
        s1 += __shfl_xor_sync(0xffffffffu, s1, o);
    }
    float rs0 = 1.f / s0, rs1 = 1.f / s1;

    // ---- store P into union region (overwrites Q) ----
    __syncthreads();
    float* sP = sU + w * (16*PST);
    #pragma unroll
    for (int nt = 0; nt < 8; nt++) {
        float* c = sc[nt];
        int r0 = grp * PST + nt*8 + 2*tig;
        *(float2*)&sP[r0]           = make_float2(c[0], c[1]);
        *(float2*)&sP[r0 + 8*PST]   = make_float2(c[2], c[3]);
    }
    __syncwarp();

    // ---- ctx: C[16x32] = P[16x64] @ V[64x32] ----
    float ao[4][4] = {};
    #pragma unroll
    for (int ks = 0; ks < 8; ks++) {
        int kk = ks * 8;
        uint32_t af[4], bf[4][2];
        af[0] = __float_as_uint(sP[grp*PST + kk + tig]);
        af[1] = __float_as_uint(sP[(grp+8)*PST + kk + tig]);
        af[2] = __float_as_uint(sP[grp*PST + kk + 4 + tig]);
        af[3] = __float_as_uint(sP[(grp+8)*PST + kk + 4 + tig]);
        #pragma unroll
        for (int nt = 0; nt < 4; nt++) {
            int r = (nt*8 + grp) * VST + w*16;
            bf[nt][0] = __float_as_uint(sVT[r + kk + tig]);
            bf[nt][1] = __float_as_uint(sVT[r + kk + 4 + tig]);
        }
        #pragma unroll
        for (int nt = 0; nt < 4; nt++)
            mma_tf32(ao[nt], af[0], af[1], af[2], af[3], bf[nt][0], bf[nt][1]);
    }

    {
        int i0 = iw + grp;
        #pragma unroll
        for (int nt = 0; nt < 4; nt++) {
            int dcol = hoff + nt*8 + 2*tig;
            float2 o0 = {ao[nt][0] * rs0, ao[nt][1] * rs0};
            float2 o1 = {ao[nt][2] * rs1, ao[nt][3] * rs1};
            *(float2*)&ctx[(size_t)(i0*NB + b)*NE + dcol] = o0;
            *(float2*)&ctx[(size_t)((i0 + 8)*NB + b)*NE + dcol] = o1;
        }
    }
}

// ---------------- layernorm (warp per row of 256, float4) ----------------
__global__ void ln_kernel(const float* __restrict__ gamma, const float* __restrict__ beta,
                          float* __restrict__ out)
{
    int row = blockIdx.x * 8 + (threadIdx.x >> 5);
    int lane = threadIdx.x & 31;
    const float* yr = g_y + (size_t)row * ND;
    float4 a = *(const float4*)&yr[lane * 4];
    float4 c = *(const float4*)&yr[128 + lane * 4];
    float s  = a.x + a.y + a.z + a.w + c.x + c.y + c.z + c.w;
    float s2 = a.x*a.x + a.y*a.y + a.z*a.z + a.w*a.w
             + c.x*c.x + c.y*c.y + c.z*c.z + c.w*c.w;
    #pragma unroll
    for (int o = 16; o >= 1; o >>= 1) {
        s  += __shfl_xor_sync(0xffffffffu, s, o);
        s2 += __shfl_xor_sync(0xffffffffu, s2, o);
    }
    float mu  = s * (1.f / ND);
    float var = s2 * (1.f / ND) - mu * mu;
    float inv = rsqrtf(var + 1e-6f);
    float4 g0 = *(const float4*)&gamma[lane * 4];
    float4 g1 = *(const float4*)&gamma[128 + lane * 4];
    float4 b0 = *(const float4*)&beta[lane * 4];
    float4 b1 = *(const float4*)&beta[128 + lane * 4];
    float4 o0 = {(a.x - mu)*inv*g0.x + b0.x, (a.y - mu)*inv*g0.y + b0.y,
                 (a.z - mu)*inv*g0.z + b0.z, (a.w - mu)*inv*g0.w + b0.w};
    float4 o1 = {(c.x - mu)*inv*g1.x + b1.x, (c.y - mu)*inv*g1.y + b1.y,
                 (c.z - mu)*inv*g1.z + b1.z, (c.w - mu)*inv*g1.w + b1.w};
    *(float4*)&out[(size_t)row * ND + lane * 4] = o0;
    *(float4*)&out[(size_t)row * ND + 128 + lane * 4] = o1;
}

// ---------------- launch ----------------
extern "C" void kernel_launch(void* const* d_in, const int* in_sizes, int n_in,
                              void* d_out, int out_size)
{
    const float* mod  = (const float*)d_in[0];
    const float* Wq   = (const float*)d_in[2];
    const float* bq   = (const float*)d_in[3];
    const float* Wk   = (const float*)d_in[4];
    const float* bk   = (const float*)d_in[5];
    const float* Wv   = (const float*)d_in[6];
    const float* bv   = (const float*)d_in[7];
    const float* Win  = (const float*)d_in[8];
    const float* bin_ = (const float*)d_in[9];
    const float* Wout = (const float*)d_in[10];
    const float* bout = (const float*)d_in[11];
    const float* Wfc  = (const float*)d_in[12];
    const float* bfc  = (const float*)d_in[13];
    const float* gamma= (const float*)d_in[14];
    const float* beta = (const float*)d_in[15];
    const int*   req  = (const int*)d_in[16];
    float* out = (float*)d_out;

    float *dWeff, *dbeff, *dWcomb, *dbcomb, *dqkv, *dctx, *dy;
    cudaGetSymbolAddress((void**)&dWeff,  g_Weff);
    cudaGetSymbolAddress((void**)&dbeff,  g_beff);
    cudaGetSymbolAddress((void**)&dWcomb, g_Wcomb);
    cudaGetSymbolAddress((void**)&dbcomb, g_bcomb);
    cudaGetSymbolAddress((void**)&dqkv,   g_qkv);
    cudaGetSymbolAddress((void**)&dctx,   g_ctx);
    cudaGetSymbolAddress((void**)&dy,     g_y);

    static int smem_set = 0;
    if (!smem_set) {
        cudaFuncSetAttribute(gemm_mma, cudaFuncAttributeMaxDynamicSharedMemorySize, GEMM_SMEM);
        cudaFuncSetAttribute(attn_mma, cudaFuncAttributeMaxDynamicSharedMemorySize, ATTN_SMEM);
        smem_set = 1;
    }

    // 1. fold weights + biases (single kernel)
    prep_gemmAB<<<dim3(4, 4, 5), 256>>>(Win, Wq, Wk, Wv, Wfc, Wout,
                                        bin_, bq, bk, bv, bout, bfc);

    // 2. fused qkv projection: [8192,256] @ [768,256]^T   (tf32, 3-stage BK=16)
    gemm_mma<<<dim3(LDQKV / 128, MROWS / 128), 256, GEMM_SMEM>>>(mod, dWeff, dbeff, nullptr, dqkv, LDQKV, ND);

    // 3. banded attention (tensor cores, 128 queries/block)
    attn_mma<<<dim3(SQ / 128, NB * NH), 256, ATTN_SMEM>>>(req, dctx);

    // 4. fused out_proj+fc with residual: ctx @ (Wfc@Wout)^T + bcomb + mod
    gemm_mma<<<dim3(ND / 128, MROWS / 128), 256, GEMM_SMEM>>>(dctx, dWcomb, dbcomb, mod, dy, ND, NE);

    // 5. layernorm
    ln_kernel<<<MROWS / 8, 256>>>(gamma, beta, out);
}

// round 13
// speedup vs baseline: 1.0035x; 1.0035x over previous
#include <cuda_runtime.h>
#include <math_constants.h>
#include <cstdint>

#define SQ 2048
#define NB 4
#define ND 256
#define NE 256
#define NH 8
#define HD 32
#define MROWS (SQ*NB)       // 8192
#define LDQKV (3*NE)        // 768

// ---------------- scratch (device globals; no allocation) ----------------
__device__ __align__(16) float g_Weff[3*NE*ND];
__device__ __align__(16) float g_beff[3*NE];
__device__ __align__(16) float g_Wcomb[ND*NE];
__device__ __align__(16) float g_bcomb[ND];
__device__ __align__(16) float g_qkv[(size_t)MROWS*LDQKV];
__device__ __align__(16) float g_ctx[(size_t)MROWS*NE];
__device__ __align__(16) float g_y[(size_t)MROWS*ND];

extern __shared__ float sdyn[];

// ---------------- helpers ----------------
__device__ __forceinline__ void mma_tf32(float c[4],
                                         uint32_t a0, uint32_t a1, uint32_t a2, uint32_t a3,
                                         uint32_t b0, uint32_t b1)
{
    asm volatile("mma.sync.aligned.m16n8k8.row.col.f32.tf32.tf32.f32 "
                 "{%0,%1,%2,%3}, {%4,%5,%6,%7}, {%8,%9}, {%0,%1,%2,%3};"
                 : "+f"(c[0]), "+f"(c[1]), "+f"(c[2]), "+f"(c[3])
                 : "r"(a0), "r"(a1), "r"(a2), "r"(a3), "r"(b0), "r"(b1));
}

__device__ __forceinline__ void cp16(void* smem_dst, const void* gmem_src) {
    uint32_t sa = (uint32_t)__cvta_generic_to_shared(smem_dst);
    asm volatile("cp.async.cg.shared.global [%0], [%1], 16;\n" :: "r"(sa), "l"(gmem_src));
}

// ---------------- prep: 4 small 256^3 products + bias folds ----------------
__global__ void prep_gemmAB(const float* __restrict__ Win,
                            const float* __restrict__ Wq, const float* __restrict__ Wk,
                            const float* __restrict__ Wv, const float* __restrict__ Wfc,
                            const float* __restrict__ Wout,
                            const float* __restrict__ bin_, const float* __restrict__ bq,
                            const float* __restrict__ bk, const float* __restrict__ bv,
                            const float* __restrict__ bout, const float* __restrict__ bfc)
{
    const int t = threadIdx.x;
    if (blockIdx.z == 4) {
        int xb = blockIdx.y * 4 + blockIdx.x;      // 0..15
        int warp = t >> 5, lane = t & 31;
        #pragma unroll
        for (int o = 0; o < 8; o++) {
            int wid = xb * 64 + warp * 8 + o;      // 0..1023
            const float* row; const float* vec; float base;
            if (wid < 3*NE) {
                int tt = wid >> 8;
                row = Win + (size_t)wid * NE;
                vec = (tt == 0) ? bq : (tt == 1) ? bk : bv;
                base = bin_[wid];
            } else {
                int r = wid - 3*NE;
                row = Wfc + (size_t)r * NE;
                vec = bout;
                base = bfc[r];
            }
            float s = 0.f;
            #pragma unroll
            for (int u = 0; u < 8; u++) s += row[u*32 + lane] * vec[u*32 + lane];
            #pragma unroll
            for (int off = 16; off >= 1; off >>= 1) s += __shfl_xor_sync(0xffffffffu, s, off);
            if (lane == 0) {
                if (wid < 3*NE) g_beff[wid] = base + s;
                else            g_bcomb[wid - 3*NE] = base + s;
            }
        }
        return;
    }

    __shared__ __align__(16) float As[16][68];   // [c][r]
    __shared__ __align__(16) float Bs[16][68];   // [c][d]
    const int tt = blockIdx.z;
    const float* A; const float* B; float* C;
    if (tt < 3) { A = Win + (size_t)tt*NE*NE; B = (tt==0)?Wq:(tt==1)?Wk:Wv; C = g_Weff + (size_t)tt*NE*ND; }
    else        { A = Wfc; B = Wout; C = g_Wcomb; }

    const int m0  = blockIdx.y * 64;
    const int d0  = blockIdx.x * 64;
    const int lrow = t >> 2;
    const int lc4  = (t & 3) << 2;
    const int brow = t >> 4;
    const int bc4  = (t & 15) << 2;
    const int ty = t >> 4, tx = t & 15;

    float acc[4][4] = {};
    for (int k0 = 0; k0 < NE; k0 += 16) {
        float4 av = *(const float4*)&A[(size_t)(m0 + lrow)*NE + k0 + lc4];
        As[lc4+0][lrow] = av.x; As[lc4+1][lrow] = av.y;
        As[lc4+2][lrow] = av.z; As[lc4+3][lrow] = av.w;
        *(float4*)&Bs[brow][bc4] = *(const float4*)&B[(size_t)(k0 + brow)*NE + d0 + bc4];
        __syncthreads();
        #pragma unroll
        for (int kk = 0; kk < 16; kk++) {
            float4 a4 = *(const float4*)&As[kk][ty << 2];
            float4 b4 = *(const float4*)&Bs[kk][tx << 2];
            float ar[4] = {a4.x, a4.y, a4.z, a4.w};
            float br[4] = {b4.x, b4.y, b4.z, b4.w};
            #pragma unroll
            for (int i = 0; i < 4; i++)
                #pragma unroll
                for (int j = 0; j < 4; j++)
                    acc[i][j] += ar[i] * br[j];
        }
        __syncthreads();
    }
    #pragma unroll
    for (int i = 0; i < 4; i++) {
        float4 o = {acc[i][0], acc[i][1], acc[i][2], acc[i][3]};
        *(float4*)&C[(size_t)(m0 + (ty<<2) + i)*NE + d0 + (tx<<2)] = o;
    }
}

// ---------------- tensor-core GEMM, 2-stage cp.async (distance 1), tile 64x128 ----------------
// C[M,N] = A[M,K] @ W[N,K]^T + bias (+resid). BK=32, 256 threads,
// 8 warps (2m x 4n), warp tile 32x32 (2 m16 x 4 n8).
// Schedule (proven R4/R5 ordering): prefetch t+1 -> other buffer, wait, sync,
// compute t, trailing sync protects buffer against next iteration's prefetch.
// Stage: A 64x36 + B 128x36 floats = 27648 B; 2 stages = 55296 B -> 3 blocks/SM budget.
#define GST 36
#define ASTAGE (64*GST)
#define BSTAGE (128*GST)
#define GSTAGE (ASTAGE + BSTAGE)
#define GEMM_SMEM (2*GSTAGE*(int)sizeof(float))   // 55296 B
__global__ void __launch_bounds__(256, 3) gemm_mma(const float* __restrict__ A,
                                                   const float* __restrict__ W,
                                                   const float* __restrict__ bias,
                                                   const float* __restrict__ resid,
                                                   float* __restrict__ C, int N, int K)
{
    const int tid = threadIdx.x;
    const int m0 = blockIdx.y * 64;
    const int n0 = blockIdx.x * 128;
    const int warp = tid >> 5;
    const int lane = tid & 31;
    const int wm = warp >> 2;       // 0..1
    const int wn = warp & 3;        // 0..3
    const int grp = lane >> 2;
    const int tig = lane & 3;
    const int ldr = tid >> 3;           // 0..31
    const int ldc = (tid & 7) << 2;     // 0..28

    const int T = K >> 5;
    float acc[2][4][4] = {};

    // prefetch stage 0
    {
        float* As = sdyn;
        float* Bs = As + ASTAGE;
        #pragma unroll
        for (int p = 0; p < 2; p++) {
            int row = ldr + p * 32;
            cp16(&As[row*GST + ldc], &A[(size_t)(m0 + row)*K + ldc]);
        }
        #pragma unroll
        for (int p = 0; p < 4; p++) {
            int row = ldr + p * 32;
            cp16(&Bs[row*GST + ldc], &W[(size_t)(n0 + row)*K + ldc]);
        }
        asm volatile("cp.async.commit_group;\n");
    }

    for (int t = 0; t < T; t++) {
        if (t + 1 < T) {
            int k0 = (t + 1) << 5;
            float* As = sdyn + ((t + 1) & 1)*GSTAGE;
            float* Bs = As + ASTAGE;
            #pragma unroll
            for (int p = 0; p < 2; p++) {
                int row = ldr + p * 32;
                cp16(&As[row*GST + ldc], &A[(size_t)(m0 + row)*K + k0 + ldc]);
            }
            #pragma unroll
            for (int p = 0; p < 4; p++) {
                int row = ldr + p * 32;
                cp16(&Bs[row*GST + ldc], &W[(size_t)(n0 + row)*K + k0 + ldc]);
            }
            asm volatile("cp.async.commit_group;\n");
            asm volatile("cp.async.wait_group 1;\n");
        } else {
            asm volatile("cp.async.wait_group 0;\n");
        }
        __syncthreads();

        const float* As = sdyn + (t & 1)*GSTAGE;
        const float* Bs = As + ASTAGE;
        #pragma unroll
        for (int kk = 0; kk < 32; kk += 8) {
            uint32_t af[2][4], bf[4][2];
            #pragma unroll
            for (int mt = 0; mt < 2; mt++) {
                int r = (wm*32 + mt*16 + grp) * GST;
                af[mt][0] = __float_as_uint(As[r + kk + tig]);
                af[mt][1] = __float_as_uint(As[r + 8*GST + kk + tig]);
                af[mt][2] = __float_as_uint(As[r + kk + 4 + tig]);
                af[mt][3] = __float_as_uint(As[r + 8*GST + kk + 4 + tig]);
            }
            #pragma unroll
            for (int nt = 0; nt < 4; nt++) {
                int c = (wn*32 + nt*8 + grp) * GST;
                bf[nt][0] = __float_as_uint(Bs[c + kk + tig]);
                bf[nt][1] = __float_as_uint(Bs[c + kk + 4 + tig]);
            }
            #pragma unroll
            for (int mt = 0; mt < 2; mt++)
                #pragma unroll
                for (int nt = 0; nt < 4; nt++)
                    mma_tf32(acc[mt][nt], af[mt][0], af[mt][1], af[mt][2], af[mt][3],
                             bf[nt][0], bf[nt][1]);
        }
        __syncthreads();   // all reads of buf (t&1) done before next prefetch overwrites it
    }

    #pragma unroll
    for (int mt = 0; mt < 2; mt++) {
        #pragma unroll
        for (int nt = 0; nt < 4; nt++) {
            int col = n0 + wn*32 + nt*8 + 2*tig;
            float bx = bias[col], by = bias[col + 1];
            int r0 = m0 + wm*32 + mt*16 + grp;
            float2 o0 = {acc[mt][nt][0] + bx, acc[mt][nt][1] + by};
            float2 o1 = {acc[mt][nt][2] + bx, acc[mt][nt][3] + by};
            if (resid) {
                float2 r0v = *(const float2*)&resid[(size_t)r0 * N + col];
                float2 r1v = *(const float2*)&resid[(size_t)(r0 + 8) * N + col];
                o0.x += r0v.x; o0.y += r0v.y;
                o1.x += r1v.x; o1.y += r1v.y;
            }
            *(float2*)&C[(size_t)r0 * N + col] = o0;
            *(float2*)&C[(size_t)(r0 + 8) * N + col] = o1;
        }
    }
}

// ---------------- banded attention via tensor cores ----------------
// Block: 128 queries x one (b,h), 256 threads (8 warps), warp owns 16 queries.
#define KST 36     // sK row stride
#define VST 180    // sVT row stride (mod 32 = 20, conflict-free frag reads)
#define QST 36     // sQ row stride
#define PST 68     // sP row stride
#define KROWS 176
#define SK_F   (KROWS*KST)           // 6336
#define SVT_F  (32*VST)              // 5760
#define SU_F   (8*16*PST)            // 8704 (>= 128*QST = 4608)
#define ATTN_SMEM ((SK_F + SVT_F + SU_F)*(int)sizeof(float))   // 83200 B
__global__ void __launch_bounds__(256) attn_mma(const int* __restrict__ reqp,
                                                float* __restrict__ ctx)
{
    float* sK  = sdyn;
    float* sVT = sdyn + SK_F;
    float* sU  = sdyn + SK_F + SVT_F;

    const float* qkv = g_qkv;
    const int req = *reqp;
    const int bh = blockIdx.y;
    const int b = bh >> 3;
    const int hoff = (bh & 7) * HD;
    const int q0 = blockIdx.x * 128;
    const int wbase = q0 - (req - 1);

    const int tid = threadIdx.x;
    const int w = tid >> 5;
    const int lane = tid & 31;
    const int grp = lane >> 2;
    const int tig = lane & 3;
    const float scale = rsqrtf((float)HD);

    #pragma unroll
    for (int u = tid; u < 128*8; u += 256) {         // Q: 128 rows x 8 float4
        int r = u >> 3, c4 = (u & 7) << 2;
        float4 v = *(const float4*)&qkv[(size_t)((q0 + r)*NB + b)*LDQKV + hoff + c4];
        sU[r*QST + c4 + 0] = v.x * scale;
        sU[r*QST + c4 + 1] = v.y * scale;
        sU[r*QST + c4 + 2] = v.z * scale;
        sU[r*QST + c4 + 3] = v.w * scale;
    }
    for (int u = tid; u < KROWS*8; u += 256) {       // K + V: 176 rows x 8 float4
        int r = u >> 3, c4 = (u & 7) << 2;
        int key = wbase + r;
        float4 kv = {0.f, 0.f, 0.f, 0.f}, vv = {0.f, 0.f, 0.f, 0.f};
        if (key >= 0 && key < SQ) {
            size_t base = (size_t)(key*NB + b)*LDQKV + hoff + c4;
            kv = *(const float4*)&qkv[base + NE];
            vv = *(const float4*)&qkv[base + 2*NE];
        }
        sK[r*KST + c4 + 0] = kv.x;
        sK[r*KST + c4 + 1] = kv.y;
        sK[r*KST + c4 + 2] = kv.z;
        sK[r*KST + c4 + 3] = kv.w;
        sVT[(c4+0)*VST + r] = vv.x;
        sVT[(c4+1)*VST + r] = vv.y;
        sVT[(c4+2)*VST + r] = vv.z;
        sVT[(c4+3)*VST + r] = vv.w;
    }
    __syncthreads();

    // ---- scores: S[16x64] = Q @ K^T ----
    float sc[8][4] = {};
    #pragma unroll
    for (int ks = 0; ks < 4; ks++) {
        int kk = ks * 8;
        uint32_t af[4], bf[8][2];
        {
            int r = (w*16 + grp) * QST;
            af[0] = __float_as_uint(sU[r + kk + tig]);
            af[1] = __float_as_uint(sU[r + 8*QST + kk + tig]);
            af[2] = __float_as_uint(sU[r + kk + 4 + tig]);
            af[3] = __float_as_uint(sU[r + 8*QST + kk + 4 + tig]);
        }
        #pragma unroll
        for (int nt = 0; nt < 8; nt++) {
            int r = (w*16 + nt*8 + grp) * KST;
            bf[nt][0] = __float_as_uint(sK[r + kk + tig]);
            bf[nt][1] = __float_as_uint(sK[r + kk + 4 + tig]);
        }
        #pragma unroll
        for (int nt = 0; nt < 8; nt++)
            mma_tf32(sc[nt], af[0], af[1], af[2], af[3], bf[nt][0], bf[nt][1]);
    }

    // ---- mask + softmax (registers) ----
    const int iw = q0 + w*16;
    const int jw = wbase + w*16;
    float mx0 = -CUDART_INF_F, mx1 = -CUDART_INF_F;
    {
        int i0 = iw + grp, i1 = i0 + 8;
        #pragma unroll
        for (int nt = 0; nt < 8; nt++) {
            int j0 = jw + nt*8 + 2*tig;
            int j1 = j0 + 1;
            bool g0 = (j0 >= 0) & (j0 < SQ);
            bool g1 = (j1 >= 0) & (j1 < SQ);
            float* c = sc[nt];
            c[0] = (g0 && abs(i0 - j0) < req) ? c[0] : -CUDART_INF_F;
            c[1] = (g1 && abs(i0 - j1) < req) ? c[1] : -CUDART_INF_F;
            c[2] = (g0 && abs(i1 - j0) < req) ? c[2] : -CUDART_INF_F;
            c[3] = (g1 && abs(i1 - j1) < req) ? c[3] : -CUDART_INF_F;
            mx0 = fmaxf(mx0, fmaxf(c[0], c[1]));
            mx1 = fmaxf(mx1, fmaxf(c[2], c[3]));
        }
    }
    #pragma unroll
    for (int o = 1; o <= 2; o <<= 1) {
        mx0 = fmaxf(mx0, __shfl_xor_sync(0xffffffffu, mx0, o));
        mx1 = fmaxf(mx1, __shfl_xor_sync(0xffffffffu, mx1, o));
    }
    float s0 = 0.f, s1 = 0.f;
    #pragma unroll
    for (int nt = 0; nt < 8; nt++) {
        float* c = sc[nt];
        c[0] = __expf(c[0] - mx0);
        c[1] = __expf(c[1] - mx0);
        c[2] = __expf(c[2] - mx1);
        c[3] = __expf(c[3] - mx1);
        s0 += c[0] + c[1];
        s1 += c[2] + c[3];
    }
    #pragma unroll
    for (int o = 1; o <= 2; o <<= 1) {
        s0 += __shfl_xor_sync(0xffffffffu, s0, o);
        s1 += __shfl_xor_sync(0xffffffffu, s1, o);
    }
    float rs0 = 1.f / s0, rs1 = 1.f / s1;

    // ---- store P into union region (overwrites Q) ----
    __syncthreads();
    float* sP = sU + w * (16*PST);
    #pragma unroll
    for (int nt = 0; nt < 8; nt++) {
        float* c = sc[nt];
        int r0 = grp * PST + nt*8 + 2*tig;
        *(float2*)&sP[r0]           = make_float2(c[0], c[1]);
        *(float2*)&sP[r0 + 8*PST]   = make_float2(c[2], c[3]);
    }
    __syncwarp();

    // ---- ctx: C[16x32] = P[16x64] @ V[64x32] ----
    float ao[4][4] = {};
    #pragma unroll
    for (int ks = 0; ks < 8; ks++) {
        int kk = ks * 8;
        uint32_t af[4], bf[4][2];
        af[0] = __float_as_uint(sP[grp*PST + kk + tig]);
        af[1] = __float_as_uint(sP[(grp+8)*PST + kk + tig]);
        af[2] = __float_as_uint(sP[grp*PST + kk + 4 + tig]);
        af[3] = __float_as_uint(sP[(grp+8)*PST + kk + 4 + tig]);
        #pragma unroll
        for (int nt = 0; nt < 4; nt++) {
            int r = (nt*8 + grp) * VST + w*16;
            bf[nt][0] = __float_as_uint(sVT[r + kk + tig]);
            bf[nt][1] = __float_as_uint(sVT[r + kk + 4 + tig]);
        }
        #pragma unroll
        for (int nt = 0; nt < 4; nt++)
            mma_tf32(ao[nt], af[0], af[1], af[2], af[3], bf[nt][0], bf[nt][1]);
    }

    {
        int i0 = iw + grp;
        #pragma unroll
        for (int nt = 0; nt < 4; nt++) {
            int dcol = hoff + nt*8 + 2*tig;
            float2 o0 = {ao[nt][0] * rs0, ao[nt][1] * rs0};
            float2 o1 = {ao[nt][2] * rs1, ao[nt][3] * rs1};
            *(float2*)&ctx[(size_t)(i0*NB + b)*NE + dcol] = o0;
            *(float2*)&ctx[(size_t)((i0 + 8)*NB + b)*NE + dcol] = o1;
        }
    }
}

// ---------------- layernorm (warp per row of 256, float4) ----------------
__global__ void ln_kernel(const float* __restrict__ gamma, const float* __restrict__ beta,
                          float* __restrict__ out)
{
    int row = blockIdx.x * 8 + (threadIdx.x >> 5);
    int lane = threadIdx.x & 31;
    const float* yr = g_y + (size_t)row * ND;
    float4 a = *(const float4*)&yr[lane * 4];
    float4 c = *(const float4*)&yr[128 + lane * 4];
    float s  = a.x + a.y + a.z + a.w + c.x + c.y + c.z + c.w;
    float s2 = a.x*a.x + a.y*a.y + a.z*a.z + a.w*a.w
             + c.x*c.x + c.y*c.y + c.z*c.z + c.w*c.w;
    #pragma unroll
    for (int o = 16; o >= 1; o >>= 1) {
        s  += __shfl_xor_sync(0xffffffffu, s, o);
        s2 += __shfl_xor_sync(0xffffffffu, s2, o);
    }
    float mu  = s * (1.f / ND);
    float var = s2 * (1.f / ND) - mu * mu;
    float inv = rsqrtf(var + 1e-6f);
    float4 g0 = *(const float4*)&gamma[lane * 4];
    float4 g1 = *(const float4*)&gamma[128 + lane * 4];
    float4 b0 = *(const float4*)&beta[lane * 4];
    float4 b1 = *(const float4*)&beta[128 + lane * 4];
    float4 o0 = {(a.x - mu)*inv*g0.x + b0.x, (a.y - mu)*inv*g0.y + b0.y,
                 (a.z - mu)*inv*g0.z + b0.z, (a.w - mu)*inv*g0.w + b0.w};
    float4 o1 = {(c.x - mu)*inv*g1.x + b1.x, (c.y - mu)*inv*g1.y + b1.y,
                 (c.z - mu)*inv*g1.z + b1.z, (c.w - mu)*inv*g1.w + b1.w};
    *(float4*)&out[(size_t)row * ND + lane * 4] = o0;
    *(float4*)&out[(size_t)row * ND + 128 + lane * 4] = o1;
}

// ---------------- launch ----------------
extern "C" void kernel_launch(void* const* d_in, const int* in_sizes, int n_in,
                              void* d_out, int out_size)
{
    const float* mod  = (const float*)d_in[0];
    const float* Wq   = (const float*)d_in[2];
    const float* bq   = (const float*)d_in[3];
    const float* Wk   = (const float*)d_in[4];
    const float* bk   = (const float*)d_in[5];
    const float* Wv   = (const float*)d_in[6];
    const float* bv   = (const float*)d_in[7];
    const float* Win  = (const float*)d_in[8];
    const float* bin_ = (const float*)d_in[9];
    const float* Wout = (const float*)d_in[10];
    const float* bout = (const float*)d_in[11];
    const float* Wfc  = (const float*)d_in[12];
    const float* bfc  = (const float*)d_in[13];
    const float* gamma= (const float*)d_in[14];
    const float* beta = (const float*)d_in[15];
    const int*   req  = (const int*)d_in[16];
    float* out = (float*)d_out;

    float *dWeff, *dbeff, *dWcomb, *dbcomb, *dqkv, *dctx, *dy;
    cudaGetSymbolAddress((void**)&dWeff,  g_Weff);
    cudaGetSymbolAddress((void**)&dbeff,  g_beff);
    cudaGetSymbolAddress((void**)&dWcomb, g_Wcomb);
    cudaGetSymbolAddress((void**)&dbcomb, g_bcomb);
    cudaGetSymbolAddress((void**)&dqkv,   g_qkv);
    cudaGetSymbolAddress((void**)&dctx,   g_ctx);
    cudaGetSymbolAddress((void**)&dy,     g_y);

    static int smem_set = 0;
    if (!smem_set) {
        cudaFuncSetAttribute(gemm_mma, cudaFuncAttributeMaxDynamicSharedMemorySize, GEMM_SMEM);
        cudaFuncSetAttribute(attn_mma, cudaFuncAttributeMaxDynamicSharedMemorySize, ATTN_SMEM);
        smem_set = 1;
    }

    // 1. fold weights + biases (single kernel)
    prep_gemmAB<<<dim3(4, 4, 5), 256>>>(Win, Wq, Wk, Wv, Wfc, Wout,
                                        bin_, bq, bk, bv, bout, bfc);

    // 2. fused qkv projection: [8192,256] @ [768,256]^T   (tf32, 64x128 tiles)
    gemm_mma<<<dim3(LDQKV / 128, MROWS / 64), 256, GEMM_SMEM>>>(mod, dWeff, dbeff, nullptr, dqkv, LDQKV, ND);

    // 3. banded attention (tensor cores, 128 queries/block)
    attn_mma<<<dim3(SQ / 128, NB * NH), 256, ATTN_SMEM>>>(req, dctx);

    // 4. fused out_proj+fc with residual: ctx @ (Wfc@Wout)^T + bcomb + mod
    gemm_mma<<<dim3(ND / 128, MROWS / 64), 256, GEMM_SMEM>>>(dctx, dWcomb, dbcomb, mod, dy, ND, NE);

    // 5. layernorm
    ln_kernel<<<MROWS / 8, 256>>>(gamma, beta, out);
}

// round 14
// speedup vs baseline: 1.0291x; 1.0255x over previous
#include <cuda_runtime.h>
#include <math_constants.h>
#include <cstdint>

#define SQ 2048
#define NB 4
#define ND 256
#define NE 256
#define NH 8
#define HD 32
#define MROWS (SQ*NB)       // 8192
#define LDQKV (3*NE)        // 768

// ---------------- scratch (device globals; no allocation) ----------------
__device__ __align__(16) float g_Weff[3*NE*ND];
__device__ __align__(16) float g_beff[3*NE];
__device__ __align__(16) float g_Wcomb[ND*NE];
__device__ __align__(16) float g_bcomb[ND];
__device__ __align__(16) float g_qkv[(size_t)MROWS*LDQKV];
__device__ __align__(16) float g_ctx[(size_t)MROWS*NE];
__device__ __align__(16) float g_y0[(size_t)MROWS*ND];   // split-K partial 0
__device__ __align__(16) float g_y1[(size_t)MROWS*ND];   // split-K partial 1

extern __shared__ float sdyn[];

// ---------------- helpers ----------------
__device__ __forceinline__ void mma_tf32(float c[4],
                                         uint32_t a0, uint32_t a1, uint32_t a2, uint32_t a3,
                                         uint32_t b0, uint32_t b1)
{
    asm volatile("mma.sync.aligned.m16n8k8.row.col.f32.tf32.tf32.f32 "
                 "{%0,%1,%2,%3}, {%4,%5,%6,%7}, {%8,%9}, {%0,%1,%2,%3};"
                 : "+f"(c[0]), "+f"(c[1]), "+f"(c[2]), "+f"(c[3])
                 : "r"(a0), "r"(a1), "r"(a2), "r"(a3), "r"(b0), "r"(b1));
}

__device__ __forceinline__ void cp16(void* smem_dst, const void* gmem_src) {
    uint32_t sa = (uint32_t)__cvta_generic_to_shared(smem_dst);
    asm volatile("cp.async.cg.shared.global [%0], [%1], 16;\n" :: "r"(sa), "l"(gmem_src));
}

// ---------------- prep: 4 small 256^3 products + bias folds ----------------
__global__ void prep_gemmAB(const float* __restrict__ Win,
                            const float* __restrict__ Wq, const float* __restrict__ Wk,
                            const float* __restrict__ Wv, const float* __restrict__ Wfc,
                            const float* __restrict__ Wout,
                            const float* __restrict__ bin_, const float* __restrict__ bq,
                            const float* __restrict__ bk, const float* __restrict__ bv,
                            const float* __restrict__ bout, const float* __restrict__ bfc)
{
    const int t = threadIdx.x;
    if (blockIdx.z == 4) {
        int xb = blockIdx.y * 4 + blockIdx.x;      // 0..15
        int warp = t >> 5, lane = t & 31;
        #pragma unroll
        for (int o = 0; o < 8; o++) {
            int wid = xb * 64 + warp * 8 + o;      // 0..1023
            const float* row; const float* vec; float base;
            if (wid < 3*NE) {
                int tt = wid >> 8;
                row = Win + (size_t)wid * NE;
                vec = (tt == 0) ? bq : (tt == 1) ? bk : bv;
                base = bin_[wid];
            } else {
                int r = wid - 3*NE;
                row = Wfc + (size_t)r * NE;
                vec = bout;
                base = bfc[r];
            }
            float s = 0.f;
            #pragma unroll
            for (int u = 0; u < 8; u++) s += row[u*32 + lane] * vec[u*32 + lane];
            #pragma unroll
            for (int off = 16; off >= 1; off >>= 1) s += __shfl_xor_sync(0xffffffffu, s, off);
            if (lane == 0) {
                if (wid < 3*NE) g_beff[wid] = base + s;
                else            g_bcomb[wid - 3*NE] = base + s;
            }
        }
        return;
    }

    __shared__ __align__(16) float As[16][68];   // [c][r]
    __shared__ __align__(16) float Bs[16][68];   // [c][d]
    const int tt = blockIdx.z;
    const float* A; const float* B; float* C;
    if (tt < 3) { A = Win + (size_t)tt*NE*NE; B = (tt==0)?Wq:(tt==1)?Wk:Wv; C = g_Weff + (size_t)tt*NE*ND; }
    else        { A = Wfc; B = Wout; C = g_Wcomb; }

    const int m0  = blockIdx.y * 64;
    const int d0  = blockIdx.x * 64;
    const int lrow = t >> 2;
    const int lc4  = (t & 3) << 2;
    const int brow = t >> 4;
    const int bc4  = (t & 15) << 2;
    const int ty = t >> 4, tx = t & 15;

    float acc[4][4] = {};
    for (int k0 = 0; k0 < NE; k0 += 16) {
        float4 av = *(const float4*)&A[(size_t)(m0 + lrow)*NE + k0 + lc4];
        As[lc4+0][lrow] = av.x; As[lc4+1][lrow] = av.y;
        As[lc4+2][lrow] = av.z; As[lc4+3][lrow] = av.w;
        *(float4*)&Bs[brow][bc4] = *(const float4*)&B[(size_t)(k0 + brow)*NE + d0 + bc4];
        __syncthreads();
        #pragma unroll
        for (int kk = 0; kk < 16; kk++) {
            float4 a4 = *(const float4*)&As[kk][ty << 2];
            float4 b4 = *(const float4*)&Bs[kk][tx << 2];
            float ar[4] = {a4.x, a4.y, a4.z, a4.w};
            float br[4] = {b4.x, b4.y, b4.z, b4.w};
            #pragma unroll
            for (int i = 0; i < 4; i++)
                #pragma unroll
                for (int j = 0; j < 4; j++)
                    acc[i][j] += ar[i] * br[j];
        }
        __syncthreads();
    }
    #pragma unroll
    for (int i = 0; i < 4; i++) {
        float4 o = {acc[i][0], acc[i][1], acc[i][2], acc[i][3]};
        *(float4*)&C[(size_t)(m0 + (ty<<2) + i)*NE + d0 + (tx<<2)] = o;
    }
}

// ---------------- tensor-core GEMM (R5-proven): 128x128, BK=32, 2-stage dist-1 ----------------
#define GST 36
#define GSTAGE (128*GST)
#define GEMM_SMEM (4*GSTAGE*(int)sizeof(float))   // 73728 B
__global__ void __launch_bounds__(256) gemm_mma(const float* __restrict__ A,
                                                const float* __restrict__ W,
                                                const float* __restrict__ bias,
                                                float* __restrict__ C, int N, int K)
{
    float* AsB = sdyn;                 // [2][128][GST]
    float* BsB = sdyn + 2*GSTAGE;      // [2][128][GST]
    const int tid = threadIdx.x;
    const int m0 = blockIdx.y * 128;
    const int n0 = blockIdx.x * 128;
    const int warp = tid >> 5;
    const int lane = tid & 31;
    const int wm = warp >> 2;
    const int wn = warp & 3;
    const int grp = lane >> 2;
    const int tig = lane & 3;
    const int ldr = tid >> 3;
    const int ldc = (tid & 7) << 2;

    const int T = K >> 5;
    float acc[4][4][4] = {};

    {
        float* As = AsB; float* Bs = BsB;
        #pragma unroll
        for (int p = 0; p < 4; p++) {
            int row = ldr + p * 32;
            cp16(&As[row*GST + ldc], &A[(size_t)(m0 + row)*K + ldc]);
            cp16(&Bs[row*GST + ldc], &W[(size_t)(n0 + row)*K + ldc]);
        }
        asm volatile("cp.async.commit_group;\n");
    }

    for (int t = 0; t < T; t++) {
        if (t + 1 < T) {
            int buf = (t + 1) & 1;
            int k0 = (t + 1) << 5;
            float* As = AsB + buf*GSTAGE;
            float* Bs = BsB + buf*GSTAGE;
            #pragma unroll
            for (int p = 0; p < 4; p++) {
                int row = ldr + p * 32;
                cp16(&As[row*GST + ldc], &A[(size_t)(m0 + row)*K + k0 + ldc]);
                cp16(&Bs[row*GST + ldc], &W[(size_t)(n0 + row)*K + k0 + ldc]);
            }
            asm volatile("cp.async.commit_group;\n");
            asm volatile("cp.async.wait_group 1;\n");
        } else {
            asm volatile("cp.async.wait_group 0;\n");
        }
        __syncthreads();

        const float* As = AsB + (t & 1)*GSTAGE;
        const float* Bs = BsB + (t & 1)*GSTAGE;
        #pragma unroll
        for (int kk = 0; kk < 32; kk += 8) {
            uint32_t af[4][4], bf[4][2];
            #pragma unroll
            for (int mt = 0; mt < 4; mt++) {
                int r = (wm*64 + mt*16 + grp) * GST;
                af[mt][0] = __float_as_uint(As[r + kk + tig]);
                af[mt][1] = __float_as_uint(As[r + 8*GST + kk + tig]);
                af[mt][2] = __float_as_uint(As[r + kk + 4 + tig]);
                af[mt][3] = __float_as_uint(As[r + 8*GST + kk + 4 + tig]);
            }
            #pragma unroll
            for (int nt = 0; nt < 4; nt++) {
                int c = (wn*32 + nt*8 + grp) * GST;
                bf[nt][0] = __float_as_uint(Bs[c + kk + tig]);
                bf[nt][1] = __float_as_uint(Bs[c + kk + 4 + tig]);
            }
            #pragma unroll
            for (int mt = 0; mt < 4; mt++)
                #pragma unroll
                for (int nt = 0; nt < 4; nt++)
                    mma_tf32(acc[mt][nt], af[mt][0], af[mt][1], af[mt][2], af[mt][3],
                             bf[nt][0], bf[nt][1]);
        }
        __syncthreads();
    }

    #pragma unroll
    for (int mt = 0; mt < 4; mt++) {
        #pragma unroll
        for (int nt = 0; nt < 4; nt++) {
            int col = n0 + wn*32 + nt*8 + 2*tig;
            float bx = bias[col], by = bias[col + 1];
            int r0 = m0 + wm*64 + mt*16 + grp;
            float2 o0 = {acc[mt][nt][0] + bx, acc[mt][nt][1] + by};
            float2 o1 = {acc[mt][nt][2] + bx, acc[mt][nt][3] + by};
            *(float2*)&C[(size_t)r0 * N + col] = o0;
            *(float2*)&C[(size_t)(r0 + 8) * N + col] = o1;
        }
    }
}

// ---------------- split-K out GEMM: partials only, no epilogue ----------------
// Cpart_z[M,N] = A[M, z*K/2 .. ] @ W[N, z*K/2 .. ]^T  (z = blockIdx.z, 4 K-tiles each)
__global__ void __launch_bounds__(256) gemm_splitk(const float* __restrict__ A,
                                                   const float* __restrict__ W,
                                                   float* __restrict__ C0,
                                                   float* __restrict__ C1,
                                                   int N, int K)
{
    float* AsB = sdyn;
    float* BsB = sdyn + 2*GSTAGE;
    const int tid = threadIdx.x;
    const int m0 = blockIdx.y * 128;
    const int n0 = blockIdx.x * 128;
    const int kz = blockIdx.z * (K >> 1);
    float* C = blockIdx.z ? C1 : C0;
    const int warp = tid >> 5;
    const int lane = tid & 31;
    const int wm = warp >> 2;
    const int wn = warp & 3;
    const int grp = lane >> 2;
    const int tig = lane & 3;
    const int ldr = tid >> 3;
    const int ldc = (tid & 7) << 2;

    const int T = K >> 6;      // tiles in this half
    float acc[4][4][4] = {};

    {
        float* As = AsB; float* Bs = BsB;
        #pragma unroll
        for (int p = 0; p < 4; p++) {
            int row = ldr + p * 32;
            cp16(&As[row*GST + ldc], &A[(size_t)(m0 + row)*K + kz + ldc]);
            cp16(&Bs[row*GST + ldc], &W[(size_t)(n0 + row)*K + kz + ldc]);
        }
        asm volatile("cp.async.commit_group;\n");
    }

    for (int t = 0; t < T; t++) {
        if (t + 1 < T) {
            int buf = (t + 1) & 1;
            int k0 = kz + ((t + 1) << 5);
            float* As = AsB + buf*GSTAGE;
            float* Bs = BsB + buf*GSTAGE;
            #pragma unroll
            for (int p = 0; p < 4; p++) {
                int row = ldr + p * 32;
                cp16(&As[row*GST + ldc], &A[(size_t)(m0 + row)*K + k0 + ldc]);
                cp16(&Bs[row*GST + ldc], &W[(size_t)(n0 + row)*K + k0 + ldc]);
            }
            asm volatile("cp.async.commit_group;\n");
            asm volatile("cp.async.wait_group 1;\n");
        } else {
            asm volatile("cp.async.wait_group 0;\n");
        }
        __syncthreads();

        const float* As = AsB + (t & 1)*GSTAGE;
        const float* Bs = BsB + (t & 1)*GSTAGE;
        #pragma unroll
        for (int kk = 0; kk < 32; kk += 8) {
            uint32_t af[4][4], bf[4][2];
            #pragma unroll
            for (int mt = 0; mt < 4; mt++) {
                int r = (wm*64 + mt*16 + grp) * GST;
                af[mt][0] = __float_as_uint(As[r + kk + tig]);
                af[mt][1] = __float_as_uint(As[r + 8*GST + kk + tig]);
                af[mt][2] = __float_as_uint(As[r + kk + 4 + tig]);
                af[mt][3] = __float_as_uint(As[r + 8*GST + kk + 4 + tig]);
            }
            #pragma unroll
            for (int nt = 0; nt < 4; nt++) {
                int c = (wn*32 + nt*8 + grp) * GST;
                bf[nt][0] = __float_as_uint(Bs[c + kk + tig]);
                bf[nt][1] = __float_as_uint(Bs[c + kk + 4 + tig]);
            }
            #pragma unroll
            for (int mt = 0; mt < 4; mt++)
                #pragma unroll
                for (int nt = 0; nt < 4; nt++)
                    mma_tf32(acc[mt][nt], af[mt][0], af[mt][1], af[mt][2], af[mt][3],
                             bf[nt][0], bf[nt][1]);
        }
        __syncthreads();
    }

    #pragma unroll
    for (int mt = 0; mt < 4; mt++) {
        #pragma unroll
        for (int nt = 0; nt < 4; nt++) {
            int col = n0 + wn*32 + nt*8 + 2*tig;
            int r0 = m0 + wm*64 + mt*16 + grp;
            *(float2*)&C[(size_t)r0 * N + col] = make_float2(acc[mt][nt][0], acc[mt][nt][1]);
            *(float2*)&C[(size_t)(r0 + 8) * N + col] = make_float2(acc[mt][nt][2], acc[mt][nt][3]);
        }
    }
}

// ---------------- banded attention via tensor cores (R5-proven) ----------------
// Block: 64 queries x one (b,h), 128 threads (4 warps), warp owns 16 queries.
#define KST 36     // sK row stride
#define VST 116    // sVT row stride
#define QST 36     // sQ row stride
#define PST 68     // sP row stride
#define KROWS 112
__global__ void __launch_bounds__(128) attn_mma(const int* __restrict__ reqp,
                                                float* __restrict__ ctx)
{
    __shared__ float sK[KROWS*KST];    // keys [wbase..wbase+112) x 32 dims
    __shared__ float sVT[32*VST];      // dims x 112 keys (transposed V)
    __shared__ float sU[4352];         // union: Q[64][36] then P[4][16][68]

    const float* qkv = g_qkv;
    const int req = *reqp;
    const int bh = blockIdx.y;
    const int b = bh >> 3;
    const int hoff = (bh & 7) * HD;
    const int q0 = blockIdx.x * 64;
    const int wbase = q0 - (req - 1);

    const int tid = threadIdx.x;
    const int w = tid >> 5;
    const int lane = tid & 31;
    const int grp = lane >> 2;
    const int tig = lane & 3;
    const float scale = rsqrtf((float)HD);

    #pragma unroll
    for (int u = tid; u < 512; u += 128) {           // Q: 64 rows x 8 float4
        int r = u >> 3, c4 = (u & 7) << 2;
        float4 v = *(const float4*)&qkv[(size_t)((q0 + r)*NB + b)*LDQKV + hoff + c4];
        sU[r*QST + c4 + 0] = v.x * scale;
        sU[r*QST + c4 + 1] = v.y * scale;
        sU[r*QST + c4 + 2] = v.z * scale;
        sU[r*QST + c4 + 3] = v.w * scale;
    }
    #pragma unroll
    for (int u = tid; u < KROWS*8; u += 128) {       // K + V: 112 rows x 8 float4
        int r = u >> 3, c4 = (u & 7) << 2;
        int key = wbase + r;
        float4 kv = {0.f, 0.f, 0.f, 0.f}, vv = {0.f, 0.f, 0.f, 0.f};
        if (key >= 0 && key < SQ) {
            size_t base = (size_t)(key*NB + b)*LDQKV + hoff + c4;
            kv = *(const float4*)&qkv[base + NE];
            vv = *(const float4*)&qkv[base + 2*NE];
        }
        sK[r*KST + c4 + 0] = kv.x;
        sK[r*KST + c4 + 1] = kv.y;
        sK[r*KST + c4 + 2] = kv.z;
        sK[r*KST + c4 + 3] = kv.w;
        sVT[(c4+0)*VST + r] = vv.x;
        sVT[(c4+1)*VST + r] = vv.y;
        sVT[(c4+2)*VST + r] = vv.z;
        sVT[(c4+3)*VST + r] = vv.w;
    }
    __syncthreads();

    // ---- scores: S[16x64] = Q @ K^T (keys wbase + w*16 + 0..63) ----
    float sc[8][4] = {};
    #pragma unroll
    for (int ks = 0; ks < 4; ks++) {
        int kk = ks * 8;
        uint32_t af[4], bf[8][2];
        {
            int r = (w*16 + grp) * QST;
            af[0] = __float_as_uint(sU[r + kk + tig]);
            af[1] = __float_as_uint(sU[r + 8*QST + kk + tig]);
            af[2] = __float_as_uint(sU[r + kk + 4 + tig]);
            af[3] = __float_as_uint(sU[r + 8*QST + kk + 4 + tig]);
        }
        #pragma unroll
        for (int nt = 0; nt < 8; nt++) {
            int r = (w*16 + nt*8 + grp) * KST;
            bf[nt][0] = __float_as_uint(sK[r + kk + tig]);
            bf[nt][1] = __float_as_uint(sK[r + kk + 4 + tig]);
        }
        #pragma unroll
        for (int nt = 0; nt < 8; nt++)
            mma_tf32(sc[nt], af[0], af[1], af[2], af[3], bf[nt][0], bf[nt][1]);
    }

    // ---- mask + softmax (registers) ----
    const int iw = q0 + w*16;
    const int jw = wbase + w*16;
    float mx0 = -CUDART_INF_F, mx1 = -CUDART_INF_F;
    {
        int i0 = iw + grp, i1 = i0 + 8;
        #pragma unroll
        for (int nt = 0; nt < 8; nt++) {
            int j0 = jw + nt*8 + 2*tig;
            int j1 = j0 + 1;
            bool g0 = (j0 >= 0) & (j0 < SQ);
            bool g1 = (j1 >= 0) & (j1 < SQ);
            float* c = sc[nt];
            c[0] = (g0 && abs(i0 - j0) < req) ? c[0] : -CUDART_INF_F;
            c[1] = (g1 && abs(i0 - j1) < req) ? c[1] : -CUDART_INF_F;
            c[2] = (g0 && abs(i1 - j0) < req) ? c[2] : -CUDART_INF_F;
            c[3] = (g1 && abs(i1 - j1) < req) ? c[3] : -CUDART_INF_F;
            mx0 = fmaxf(mx0, fmaxf(c[0], c[1]));
            mx1 = fmaxf(mx1, fmaxf(c[2], c[3]));
        }
    }
    #pragma unroll
    for (int o = 1; o <= 2; o <<= 1) {
        mx0 = fmaxf(mx0, __shfl_xor_sync(0xffffffffu, mx0, o));
        mx1 = fmaxf(mx1, __shfl_xor_sync(0xffffffffu, mx1, o));
    }
    float s0 = 0.f, s1 = 0.f;
    #pragma unroll
    for (int nt = 0; nt < 8; nt++) {
        float* c = sc[nt];
        c[0] = __expf(c[0] - mx0);
        c[1] = __expf(c[1] - mx0);
        c[2] = __expf(c[2] - mx1);
        c[3] = __expf(c[3] - mx1);
        s0 += c[0] + c[1];
        s1 += c[2] + c[3];
    }
    #pragma unroll
    for (int o = 1; o <= 2; o <<= 1) {
        s0 += __shfl_xor_sync(0xffffffffu, s0, o);
        s1 += __shfl_xor_sync(0xffffffffu, s1, o);
    }
    float rs0 = 1.f / s0, rs1 = 1.f / s1;

    // ---- store P into union region (overwrites Q) ----
    __syncthreads();
    float* sP = sU + w * (16*PST);
    #pragma unroll
    for (int nt = 0; nt < 8; nt++) {
        float* c = sc[nt];
        int r0 = grp * PST + nt*8 + 2*tig;
        *(float2*)&sP[r0]           = make_float2(c[0], c[1]);
        *(float2*)&sP[r0 + 8*PST]   = make_float2(c[2], c[3]);
    }
    __syncwarp();

    // ---- ctx: C[16x32] = P[16x64] @ V[64x32] ----
    float ao[4][4] = {};
    #pragma unroll
    for (int ks = 0; ks < 8; ks++) {
        int kk = ks * 8;
        uint32_t af[4], bf[4][2];
        af[0] = __float_as_uint(sP[grp*PST + kk + tig]);
        af[1] = __float_as_uint(sP[(grp+8)*PST + kk + tig]);
        af[2] = __float_as_uint(sP[grp*PST + kk + 4 + tig]);
        af[3] = __float_as_uint(sP[(grp+8)*PST + kk + 4 + tig]);
        #pragma unroll
        for (int nt = 0; nt < 4; nt++) {
            int r = (nt*8 + grp) * VST + w*16;
            bf[nt][0] = __float_as_uint(sVT[r + kk + tig]);
            bf[nt][1] = __float_as_uint(sVT[r + kk + 4 + tig]);
        }
        #pragma unroll
        for (int nt = 0; nt < 4; nt++)
            mma_tf32(ao[nt], af[0], af[1], af[2], af[3], bf[nt][0], bf[nt][1]);
    }

    {
        int i0 = iw + grp;
        #pragma unroll
        for (int nt = 0; nt < 4; nt++) {
            int dcol = hoff + nt*8 + 2*tig;
            float2 o0 = {ao[nt][0] * rs0, ao[nt][1] * rs0};
            float2 o1 = {ao[nt][2] * rs1, ao[nt][3] * rs1};
            *(float2*)&ctx[(size_t)(i0*NB + b)*NE + dcol] = o0;
            *(float2*)&ctx[(size_t)((i0 + 8)*NB + b)*NE + dcol] = o1;
        }
    }
}

// ---------------- fused split-K reduce + bias + residual + layernorm ----------------
__global__ void ln_fused(const float* __restrict__ mod,
                         const float* __restrict__ gamma, const float* __restrict__ beta,
                         float* __restrict__ out)
{
    int row = blockIdx.x * 8 + (threadIdx.x >> 5);
    int lane = threadIdx.x & 31;
    size_t base = (size_t)row * ND;
    int c0 = lane * 4, c1 = 128 + lane * 4;

    float4 p0a = *(const float4*)&g_y0[base + c0];
    float4 p0c = *(const float4*)&g_y0[base + c1];
    float4 p1a = *(const float4*)&g_y1[base + c0];
    float4 p1c = *(const float4*)&g_y1[base + c1];
    float4 ma  = *(const float4*)&mod[base + c0];
    float4 mc  = *(const float4*)&mod[base + c1];
    float4 ba  = *(const float4*)&g_bcomb[c0];
    float4 bc  = *(const float4*)&g_bcomb[c1];

    float4 a = {p0a.x + p1a.x + ma.x + ba.x, p0a.y + p1a.y + ma.y + ba.y,
                p0a.z + p1a.z + ma.z + ba.z, p0a.w + p1a.w + ma.w + ba.w};
    float4 c = {p0c.x + p1c.x + mc.x + bc.x, p0c.y + p1c.y + mc.y + bc.y,
                p0c.z + p1c.z + mc.z + bc.z, p0c.w + p1c.w + mc.w + bc.w};

    float s  = a.x + a.y + a.z + a.w + c.x + c.y + c.z + c.w;
    float s2 = a.x*a.x + a.y*a.y + a.z*a.z + a.w*a.w
             + c.x*c.x + c.y*c.y + c.z*c.z + c.w*c.w;
    #pragma unroll
    for (int o = 16; o >= 1; o >>= 1) {
        s  += __shfl_xor_sync(0xffffffffu, s, o);
        s2 += __shfl_xor_sync(0xffffffffu, s2, o);
    }
    float mu  = s * (1.f / ND);
    float var = s2 * (1.f / ND) - mu * mu;
    float inv = rsqrtf(var + 1e-6f);
    float4 g0 = *(const float4*)&gamma[c0];
    float4 g1 = *(const float4*)&gamma[c1];
    float4 b0 = *(const float4*)&beta[c0];
    float4 b1 = *(const float4*)&beta[c1];
    float4 o0 = {(a.x - mu)*inv*g0.x + b0.x, (a.y - mu)*inv*g0.y + b0.y,
                 (a.z - mu)*inv*g0.z + b0.z, (a.w - mu)*inv*g0.w + b0.w};
    float4 o1 = {(c.x - mu)*inv*g1.x + b1.x, (c.y - mu)*inv*g1.y + b1.y,
                 (c.z - mu)*inv*g1.z + b1.z, (c.w - mu)*inv*g1.w + b1.w};
    *(float4*)&out[base + c0] = o0;
    *(float4*)&out[base + c1] = o1;
}

// ---------------- launch ----------------
extern "C" void kernel_launch(void* const* d_in, const int* in_sizes, int n_in,
                              void* d_out, int out_size)
{
    const float* mod  = (const float*)d_in[0];
    const float* Wq   = (const float*)d_in[2];
    const float* bq   = (const float*)d_in[3];
    const float* Wk   = (const float*)d_in[4];
    const float* bk   = (const float*)d_in[5];
    const float* Wv   = (const float*)d_in[6];
    const float* bv   = (const float*)d_in[7];
    const float* Win  = (const float*)d_in[8];
    const float* bin_ = (const float*)d_in[9];
    const float* Wout = (const float*)d_in[10];
    const float* bout = (const float*)d_in[11];
    const float* Wfc  = (const float*)d_in[12];
    const float* bfc  = (const float*)d_in[13];
    const float* gamma= (const float*)d_in[14];
    const float* beta = (const float*)d_in[15];
    const int*   req  = (const int*)d_in[16];
    float* out = (float*)d_out;

    float *dWeff, *dbeff, *dWcomb, *dqkv, *dctx, *dy0, *dy1;
    cudaGetSymbolAddress((void**)&dWeff,  g_Weff);
    cudaGetSymbolAddress((void**)&dbeff,  g_beff);
    cudaGetSymbolAddress((void**)&dWcomb, g_Wcomb);
    cudaGetSymbolAddress((void**)&dqkv,   g_qkv);
    cudaGetSymbolAddress((void**)&dctx,   g_ctx);
    cudaGetSymbolAddress((void**)&dy0,    g_y0);
    cudaGetSymbolAddress((void**)&dy1,    g_y1);

    static int smem_set = 0;
    if (!smem_set) {
        cudaFuncSetAttribute(gemm_mma,    cudaFuncAttributeMaxDynamicSharedMemorySize, GEMM_SMEM);
        cudaFuncSetAttribute(gemm_splitk, cudaFuncAttributeMaxDynamicSharedMemorySize, GEMM_SMEM);
        smem_set = 1;
    }

    // 1. fold weights + biases
    prep_gemmAB<<<dim3(4, 4, 5), 256>>>(Win, Wq, Wk, Wv, Wfc, Wout,
                                        bin_, bq, bk, bv, bout, bfc);

    // 2. fused qkv projection: [8192,256] @ [768,256]^T   (tf32, R5-proven)
    gemm_mma<<<dim3(LDQKV / 128, MROWS / 128), 256, GEMM_SMEM>>>(mod, dWeff, dbeff, dqkv, LDQKV, ND);

    // 3. banded attention (tensor cores, R5-proven 64-query blocks)
    attn_mma<<<dim3(SQ / 64, NB * NH), 128>>>(req, dctx);

    // 4. out_proj+fc, split-K=2 partials: ctx @ (Wfc@Wout)^T
    gemm_splitk<<<dim3(ND / 128, MROWS / 128, 2), 256, GEMM_SMEM>>>(dctx, dWcomb, dy0, dy1, ND, NE);

    // 5. fused reduce + bias + residual + layernorm
    ln_fused<<<MROWS / 8, 256>>>(mod, gamma, beta, out);
}

// round 15
// speedup vs baseline: 1.2103x; 1.1761x over previous
#include <cuda_runtime.h>
#include <math_constants.h>
#include <cstdint>

#define SQ 2048
#define NB 4
#define ND 256
#define NE 256
#define NH 8
#define HD 32
#define MROWS (SQ*NB)       // 8192
#define LDQKV (3*NE)        // 768
#define KH 128              // K/2 in packed bf16x2 units (K=256)

// ---------------- scratch (device globals; no allocation) ----------------
__device__ __align__(16) uint32_t g_Weffh[3*NE*KH];    // bf16x2-packed (Win_t@Wt)
__device__ __align__(16) uint32_t g_Wcombh[ND*KH];     // bf16x2-packed (Wfc@Wout)
__device__ __align__(16) uint32_t g_modh[(size_t)MROWS*KH];   // bf16x2 mod
__device__ __align__(16) uint32_t g_ctxh[(size_t)MROWS*KH];   // bf16x2 ctx
__device__ __align__(16) float g_beff[3*NE];
__device__ __align__(16) float g_bcomb[ND];
__device__ __align__(16) float g_qkv[(size_t)MROWS*LDQKV];
__device__ __align__(16) float g_y[(size_t)MROWS*ND];

extern __shared__ float sdyn[];

// ---------------- helpers ----------------
__device__ __forceinline__ void mma_tf32(float c[4],
                                         uint32_t a0, uint32_t a1, uint32_t a2, uint32_t a3,
                                         uint32_t b0, uint32_t b1)
{
    asm volatile("mma.sync.aligned.m16n8k8.row.col.f32.tf32.tf32.f32 "
                 "{%0,%1,%2,%3}, {%4,%5,%6,%7}, {%8,%9}, {%0,%1,%2,%3};"
                 : "+f"(c[0]), "+f"(c[1]), "+f"(c[2]), "+f"(c[3])
                 : "r"(a0), "r"(a1), "r"(a2), "r"(a3), "r"(b0), "r"(b1));
}

__device__ __forceinline__ void mma_bf16(float c[4],
                                         uint32_t a0, uint32_t a1, uint32_t a2, uint32_t a3,
                                         uint32_t b0, uint32_t b1)
{
    asm volatile("mma.sync.aligned.m16n8k16.row.col.f32.bf16.bf16.f32 "
                 "{%0,%1,%2,%3}, {%4,%5,%6,%7}, {%8,%9}, {%0,%1,%2,%3};"
                 : "+f"(c[0]), "+f"(c[1]), "+f"(c[2]), "+f"(c[3])
                 : "r"(a0), "r"(a1), "r"(a2), "r"(a3), "r"(b0), "r"(b1));
}

// pack two fp32 into bf16x2: low half = lo (even k), high half = hi (odd k)
__device__ __forceinline__ uint32_t pack_bf16(float lo, float hi) {
    uint32_t r;
    asm("cvt.rn.bf16x2.f32 %0, %1, %2;" : "=r"(r) : "f"(hi), "f"(lo));
    return r;
}

__device__ __forceinline__ void cp16(void* smem_dst, const void* gmem_src) {
    uint32_t sa = (uint32_t)__cvta_generic_to_shared(smem_dst);
    asm volatile("cp.async.cg.shared.global [%0], [%1], 16;\n" :: "r"(sa), "l"(gmem_src));
}

// ---------------- fp32 -> packed bf16x2 conversion (mod) ----------------
__global__ void cvt_bf16_kernel(const float* __restrict__ in, uint32_t* __restrict__ out)
{
    int i = blockIdx.x * 256 + threadIdx.x;           // one float4 per thread
    float4 v = *(const float4*)&in[(size_t)i * 4];
    out[(size_t)i*2 + 0] = pack_bf16(v.x, v.y);
    out[(size_t)i*2 + 1] = pack_bf16(v.z, v.w);
}

// ---------------- prep: 4 small 256^3 products (bf16 out) + bias folds ----------------
__global__ void prep_gemmAB(const float* __restrict__ Win,
                            const float* __restrict__ Wq, const float* __restrict__ Wk,
                            const float* __restrict__ Wv, const float* __restrict__ Wfc,
                            const float* __restrict__ Wout,
                            const float* __restrict__ bin_, const float* __restrict__ bq,
                            const float* __restrict__ bk, const float* __restrict__ bv,
                            const float* __restrict__ bout, const float* __restrict__ bfc)
{
    const int t = threadIdx.x;
    if (blockIdx.z == 4) {
        int xb = blockIdx.y * 4 + blockIdx.x;      // 0..15
        int warp = t >> 5, lane = t & 31;
        #pragma unroll
        for (int o = 0; o < 8; o++) {
            int wid = xb * 64 + warp * 8 + o;      // 0..1023
            const float* row; const float* vec; float base;
            if (wid < 3*NE) {
                int tt = wid >> 8;
                row = Win + (size_t)wid * NE;
                vec = (tt == 0) ? bq : (tt == 1) ? bk : bv;
                base = bin_[wid];
            } else {
                int r = wid - 3*NE;
                row = Wfc + (size_t)r * NE;
                vec = bout;
                base = bfc[r];
            }
            float s = 0.f;
            #pragma unroll
            for (int u = 0; u < 8; u++) s += row[u*32 + lane] * vec[u*32 + lane];
            #pragma unroll
            for (int off = 16; off >= 1; off >>= 1) s += __shfl_xor_sync(0xffffffffu, s, off);
            if (lane == 0) {
                if (wid < 3*NE) g_beff[wid] = base + s;
                else            g_bcomb[wid - 3*NE] = base + s;
            }
        }
        return;
    }

    __shared__ __align__(16) float As[16][68];   // [c][r]
    __shared__ __align__(16) float Bs[16][68];   // [c][d]
    const int tt = blockIdx.z;
    const float* A; const float* B; uint32_t* Ch;
    if (tt < 3) { A = Win + (size_t)tt*NE*NE; B = (tt==0)?Wq:(tt==1)?Wk:Wv; Ch = g_Weffh + (size_t)tt*NE*KH; }
    else        { A = Wfc; B = Wout; Ch = g_Wcombh; }

    const int m0  = blockIdx.y * 64;
    const int d0  = blockIdx.x * 64;
    const int lrow = t >> 2;
    const int lc4  = (t & 3) << 2;
    const int brow = t >> 4;
    const int bc4  = (t & 15) << 2;
    const int ty = t >> 4, tx = t & 15;

    float acc[4][4] = {};
    for (int k0 = 0; k0 < NE; k0 += 16) {
        float4 av = *(const float4*)&A[(size_t)(m0 + lrow)*NE + k0 + lc4];
        As[lc4+0][lrow] = av.x; As[lc4+1][lrow] = av.y;
        As[lc4+2][lrow] = av.z; As[lc4+3][lrow] = av.w;
        *(float4*)&Bs[brow][bc4] = *(const float4*)&B[(size_t)(k0 + brow)*NE + d0 + bc4];
        __syncthreads();
        #pragma unroll
        for (int kk = 0; kk < 16; kk++) {
            float4 a4 = *(const float4*)&As[kk][ty << 2];
            float4 b4 = *(const float4*)&Bs[kk][tx << 2];
            float ar[4] = {a4.x, a4.y, a4.z, a4.w};
            float br[4] = {b4.x, b4.y, b4.z, b4.w};
            #pragma unroll
            for (int i = 0; i < 4; i++)
                #pragma unroll
                for (int j = 0; j < 4; j++)
                    acc[i][j] += ar[i] * br[j];
        }
        __syncthreads();
    }
    #pragma unroll
    for (int i = 0; i < 4; i++) {
        uint32_t u0 = pack_bf16(acc[i][0], acc[i][1]);
        uint32_t u1 = pack_bf16(acc[i][2], acc[i][3]);
        *(uint2*)&Ch[(size_t)(m0 + (ty<<2) + i)*KH + ((d0 + (tx<<2)) >> 1)] = make_uint2(u0, u1);
    }
}

// ---------------- bf16 tensor-core GEMM: 128x128, BK=32, 2-stage dist-1 ----------------
// C[M,N] = A[M,K] @ W[N,K]^T + bias (+resid). A,W packed bf16x2 [.][K/2] uint32.
// 256 threads, 8 warps (2m x 4n), warp tile 64x32, mma m16n8k16.
#define ST2 20
#define HSTAGE (128*ST2)
#define GEMM_SMEM (4*HSTAGE*(int)sizeof(uint32_t))   // 40960 B
__global__ void __launch_bounds__(256) gemm_h(const uint32_t* __restrict__ A,
                                              const uint32_t* __restrict__ W,
                                              const float* __restrict__ bias,
                                              const float* __restrict__ resid,
                                              float* __restrict__ C, int N, int K2)
{
    uint32_t* AsB = (uint32_t*)sdyn;           // [2][128][ST2]
    uint32_t* BsB = AsB + 2*HSTAGE;            // [2][128][ST2]
    const int tid = threadIdx.x;
    const int m0 = blockIdx.y * 128;
    const int n0 = blockIdx.x * 128;
    const int warp = tid >> 5;
    const int lane = tid & 31;
    const int wm = warp >> 2;
    const int wn = warp & 3;
    const int grp = lane >> 2;
    const int tig = lane & 3;
    const int ldr = tid >> 2;             // 0..63
    const int ldc2 = (tid & 3) << 2;      // 0,4,8,12 (uint32 cols)

    const int T = K2 >> 4;                // 16 uint32 = 32 K per tile
    float acc[4][4][4] = {};

    // prefetch stage 0
    {
        uint32_t* As = AsB; uint32_t* Bs = BsB;
        #pragma unroll
        for (int p = 0; p < 2; p++) {
            int row = ldr + p * 64;
            cp16(&As[row*ST2 + ldc2], &A[(size_t)(m0 + row)*K2 + ldc2]);
            cp16(&Bs[row*ST2 + ldc2], &W[(size_t)(n0 + row)*K2 + ldc2]);
        }
        asm volatile("cp.async.commit_group;\n");
    }

    for (int t = 0; t < T; t++) {
        if (t + 1 < T) {
            int buf = (t + 1) & 1;
            int k2 = (t + 1) << 4;
            uint32_t* As = AsB + buf*HSTAGE;
            uint32_t* Bs = BsB + buf*HSTAGE;
            #pragma unroll
            for (int p = 0; p < 2; p++) {
                int row = ldr + p * 64;
                cp16(&As[row*ST2 + ldc2], &A[(size_t)(m0 + row)*K2 + k2 + ldc2]);
                cp16(&Bs[row*ST2 + ldc2], &W[(size_t)(n0 + row)*K2 + k2 + ldc2]);
            }
            asm volatile("cp.async.commit_group;\n");
            asm volatile("cp.async.wait_group 1;\n");
        } else {
            asm volatile("cp.async.wait_group 0;\n");
        }
        __syncthreads();

        const uint32_t* As = AsB + (t & 1)*HSTAGE;
        const uint32_t* Bs = BsB + (t & 1)*HSTAGE;
        #pragma unroll
        for (int kp = 0; kp < 16; kp += 8) {       // two k16 steps per tile
            uint32_t af[4][4], bf[4][2];
            #pragma unroll
            for (int mt = 0; mt < 4; mt++) {
                int r = (wm*64 + mt*16 + grp) * ST2;
                af[mt][0] = As[r + kp + tig];
                af[mt][1] = As[r + 8*ST2 + kp + tig];
                af[mt][2] = As[r + kp + 4 + tig];
                af[mt][3] = As[r + 8*ST2 + kp + 4 + tig];
            }
            #pragma unroll
            for (int nt = 0; nt < 4; nt++) {
                int c = (wn*32 + nt*8 + grp) * ST2;
                bf[nt][0] = Bs[c + kp + tig];
                bf[nt][1] = Bs[c + kp + 4 + tig];
            }
            #pragma unroll
            for (int mt = 0; mt < 4; mt++)
                #pragma unroll
                for (int nt = 0; nt < 4; nt++)
                    mma_bf16(acc[mt][nt], af[mt][0], af[mt][1], af[mt][2], af[mt][3],
                             bf[nt][0], bf[nt][1]);
        }
        __syncthreads();
    }

    #pragma unroll
    for (int mt = 0; mt < 4; mt++) {
        #pragma unroll
        for (int nt = 0; nt < 4; nt++) {
            int col = n0 + wn*32 + nt*8 + 2*tig;
            float bx = bias[col], by = bias[col + 1];
            int r0 = m0 + wm*64 + mt*16 + grp;
            float2 o0 = {acc[mt][nt][0] + bx, acc[mt][nt][1] + by};
            float2 o1 = {acc[mt][nt][2] + bx, acc[mt][nt][3] + by};
            if (resid) {
                float2 r0v = *(const float2*)&resid[(size_t)r0 * N + col];
                float2 r1v = *(const float2*)&resid[(size_t)(r0 + 8) * N + col];
                o0.x += r0v.x; o0.y += r0v.y;
                o1.x += r1v.x; o1.y += r1v.y;
            }
            *(float2*)&C[(size_t)r0 * N + col] = o0;
            *(float2*)&C[(size_t)(r0 + 8) * N + col] = o1;
        }
    }
}

// ---------------- banded attention via tensor cores (R5-proven, ctx out bf16) ----------------
// Block: 64 queries x one (b,h), 128 threads (4 warps), warp owns 16 queries.
#define KST 36     // sK row stride
#define VST 116    // sVT row stride
#define QST 36     // sQ row stride
#define PST 68     // sP row stride
#define KROWS 112
__global__ void __launch_bounds__(128) attn_mma(const int* __restrict__ reqp,
                                                uint32_t* __restrict__ ctxh)
{
    __shared__ float sK[KROWS*KST];    // keys [wbase..wbase+112) x 32 dims
    __shared__ float sVT[32*VST];      // dims x 112 keys (transposed V)
    __shared__ float sU[4352];         // union: Q[64][36] then P[4][16][68]

    const float* qkv = g_qkv;
    const int req = *reqp;
    const int bh = blockIdx.y;
    const int b = bh >> 3;
    const int hoff = (bh & 7) * HD;
    const int q0 = blockIdx.x * 64;
    const int wbase = q0 - (req - 1);

    const int tid = threadIdx.x;
    const int w = tid >> 5;
    const int lane = tid & 31;
    const int grp = lane >> 2;
    const int tig = lane & 3;
    const float scale = rsqrtf((float)HD);

    #pragma unroll
    for (int u = tid; u < 512; u += 128) {           // Q: 64 rows x 8 float4
        int r = u >> 3, c4 = (u & 7) << 2;
        float4 v = *(const float4*)&qkv[(size_t)((q0 + r)*NB + b)*LDQKV + hoff + c4];
        sU[r*QST + c4 + 0] = v.x * scale;
        sU[r*QST + c4 + 1] = v.y * scale;
        sU[r*QST + c4 + 2] = v.z * scale;
        sU[r*QST + c4 + 3] = v.w * scale;
    }
    #pragma unroll
    for (int u = tid; u < KROWS*8; u += 128) {       // K + V: 112 rows x 8 float4
        int r = u >> 3, c4 = (u & 7) << 2;
        int key = wbase + r;
        float4 kv = {0.f, 0.f, 0.f, 0.f}, vv = {0.f, 0.f, 0.f, 0.f};
        if (key >= 0 && key < SQ) {
            size_t base = (size_t)(key*NB + b)*LDQKV + hoff + c4;
            kv = *(const float4*)&qkv[base + NE];
            vv = *(const float4*)&qkv[base + 2*NE];
        }
        sK[r*KST + c4 + 0] = kv.x;
        sK[r*KST + c4 + 1] = kv.y;
        sK[r*KST + c4 + 2] = kv.z;
        sK[r*KST + c4 + 3] = kv.w;
        sVT[(c4+0)*VST + r] = vv.x;
        sVT[(c4+1)*VST + r] = vv.y;
        sVT[(c4+2)*VST + r] = vv.z;
        sVT[(c4+3)*VST + r] = vv.w;
    }
    __syncthreads();

    // ---- scores: S[16x64] = Q @ K^T (keys wbase + w*16 + 0..63) ----
    float sc[8][4] = {};
    #pragma unroll
    for (int ks = 0; ks < 4; ks++) {
        int kk = ks * 8;
        uint32_t af[4], bf[8][2];
        {
            int r = (w*16 + grp) * QST;
            af[0] = __float_as_uint(sU[r + kk + tig]);
            af[1] = __float_as_uint(sU[r + 8*QST + kk + tig]);
            af[2] = __float_as_uint(sU[r + kk + 4 + tig]);
            af[3] = __float_as_uint(sU[r + 8*QST + kk + 4 + tig]);
        }
        #pragma unroll
        for (int nt = 0; nt < 8; nt++) {
            int r = (w*16 + nt*8 + grp) * KST;
            bf[nt][0] = __float_as_uint(sK[r + kk + tig]);
            bf[nt][1] = __float_as_uint(sK[r + kk + 4 + tig]);
        }
        #pragma unroll
        for (int nt = 0; nt < 8; nt++)
            mma_tf32(sc[nt], af[0], af[1], af[2], af[3], bf[nt][0], bf[nt][1]);
    }

    // ---- mask + softmax (registers) ----
    const int iw = q0 + w*16;
    const int jw = wbase + w*16;
    float mx0 = -CUDART_INF_F, mx1 = -CUDART_INF_F;
    {
        int i0 = iw + grp, i1 = i0 + 8;
        #pragma unroll
        for (int nt = 0; nt < 8; nt++) {
            int j0 = jw + nt*8 + 2*tig;
            int j1 = j0 + 1;
            bool g0 = (j0 >= 0) & (j0 < SQ);
            bool g1 = (j1 >= 0) & (j1 < SQ);
            float* c = sc[nt];
            c[0] = (g0 && abs(i0 - j0) < req) ? c[0] : -CUDART_INF_F;
            c[1] = (g1 && abs(i0 - j1) < req) ? c[1] : -CUDART_INF_F;
            c[2] = (g0 && abs(i1 - j0) < req) ? c[2] : -CUDART_INF_F;
            c[3] = (g1 && abs(i1 - j1) < req) ? c[3] : -CUDART_INF_F;
            mx0 = fmaxf(mx0, fmaxf(c[0], c[1]));
            mx1 = fmaxf(mx1, fmaxf(c[2], c[3]));
        }
    }
    #pragma unroll
    for (int o = 1; o <= 2; o <<= 1) {
        mx0 = fmaxf(mx0, __shfl_xor_sync(0xffffffffu, mx0, o));
        mx1 = fmaxf(mx1, __shfl_xor_sync(0xffffffffu, mx1, o));
    }
    float s0 = 0.f, s1 = 0.f;
    #pragma unroll
    for (int nt = 0; nt < 8; nt++) {
        float* c = sc[nt];
        c[0] = __expf(c[0] - mx0);
        c[1] = __expf(c[1] - mx0);
        c[2] = __expf(c[2] - mx1);
        c[3] = __expf(c[3] - mx1);
        s0 += c[0] + c[1];
        s1 += c[2] + c[3];
    }
    #pragma unroll
    for (int o = 1; o <= 2; o <<= 1) {
        s0 += __shfl_xor_sync(0xffffffffu, s0, o);
        s1 += __shfl_xor_sync(0xffffffffu, s1, o);
    }
    float rs0 = 1.f / s0, rs1 = 1.f / s1;

    // ---- store P into union region (overwrites Q) ----
    __syncthreads();
    float* sP = sU + w * (16*PST);
    #pragma unroll
    for (int nt = 0; nt < 8; nt++) {
        float* c = sc[nt];
        int r0 = grp * PST + nt*8 + 2*tig;
        *(float2*)&sP[r0]           = make_float2(c[0], c[1]);
        *(float2*)&sP[r0 + 8*PST]   = make_float2(c[2], c[3]);
    }
    __syncwarp();

    // ---- ctx: C[16x32] = P[16x64] @ V[64x32] ----
    float ao[4][4] = {};
    #pragma unroll
    for (int ks = 0; ks < 8; ks++) {
        int kk = ks * 8;
        uint32_t af[4], bf[4][2];
        af[0] = __float_as_uint(sP[grp*PST + kk + tig]);
        af[1] = __float_as_uint(sP[(grp+8)*PST + kk + tig]);
        af[2] = __float_as_uint(sP[grp*PST + kk + 4 + tig]);
        af[3] = __float_as_uint(sP[(grp+8)*PST + kk + 4 + tig]);
        #pragma unroll
        for (int nt = 0; nt < 4; nt++) {
            int r = (nt*8 + grp) * VST + w*16;
            bf[nt][0] = __float_as_uint(sVT[r + kk + tig]);
            bf[nt][1] = __float_as_uint(sVT[r + kk + 4 + tig]);
        }
        #pragma unroll
        for (int nt = 0; nt < 4; nt++)
            mma_tf32(ao[nt], af[0], af[1], af[2], af[3], bf[nt][0], bf[nt][1]);
    }

    // ---- epilogue: divide by row sums, write ctx as packed bf16x2 ----
    {
        int i0 = iw + grp;
        #pragma unroll
        for (int nt = 0; nt < 4; nt++) {
            int dcol = hoff + nt*8 + 2*tig;     // even
            ctxh[(size_t)(i0*NB + b)*KH + (dcol >> 1)] =
                pack_bf16(ao[nt][0] * rs0, ao[nt][1] * rs0);
            ctxh[(size_t)((i0 + 8)*NB + b)*KH + (dcol >> 1)] =
                pack_bf16(ao[nt][2] * rs1, ao[nt][3] * rs1);
        }
    }
}

// ---------------- layernorm (warp per row of 256, float4) ----------------
__global__ void ln_kernel(const float* __restrict__ gamma, const float* __restrict__ beta,
                          float* __restrict__ out)
{
    int row = blockIdx.x * 8 + (threadIdx.x >> 5);
    int lane = threadIdx.x & 31;
    const float* yr = g_y + (size_t)row * ND;
    float4 a = *(const float4*)&yr[lane * 4];
    float4 c = *(const float4*)&yr[128 + lane * 4];
    float s  = a.x + a.y + a.z + a.w + c.x + c.y + c.z + c.w;
    float s2 = a.x*a.x + a.y*a.y + a.z*a.z + a.w*a.w
             + c.x*c.x + c.y*c.y + c.z*c.z + c.w*c.w;
    #pragma unroll
    for (int o = 16; o >= 1; o >>= 1) {
        s  += __shfl_xor_sync(0xffffffffu, s, o);
        s2 += __shfl_xor_sync(0xffffffffu, s2, o);
    }
    float mu  = s * (1.f / ND);
    float var = s2 * (1.f / ND) - mu * mu;
    float inv = rsqrtf(var + 1e-6f);
    float4 g0 = *(const float4*)&gamma[lane * 4];
    float4 g1 = *(const float4*)&gamma[128 + lane * 4];
    float4 b0 = *(const float4*)&beta[lane * 4];
    float4 b1 = *(const float4*)&beta[128 + lane * 4];
    float4 o0 = {(a.x - mu)*inv*g0.x + b0.x, (a.y - mu)*inv*g0.y + b0.y,
                 (a.z - mu)*inv*g0.z + b0.z, (a.w - mu)*inv*g0.w + b0.w};
    float4 o1 = {(c.x - mu)*inv*g1.x + b1.x, (c.y - mu)*inv*g1.y + b1.y,
                 (c.z - mu)*inv*g1.z + b1.z, (c.w - mu)*inv*g1.w + b1.w};
    *(float4*)&out[(size_t)row * ND + lane * 4] = o0;
    *(float4*)&out[(size_t)row * ND + 128 + lane * 4] = o1;
}

// ---------------- launch ----------------
extern "C" void kernel_launch(void* const* d_in, const int* in_sizes, int n_in,
                              void* d_out, int out_size)
{
    const float* mod  = (const float*)d_in[0];
    const float* Wq   = (const float*)d_in[2];
    const float* bq   = (const float*)d_in[3];
    const float* Wk   = (const float*)d_in[4];
    const float* bk   = (const float*)d_in[5];
    const float* Wv   = (const float*)d_in[6];
    const float* bv   = (const float*)d_in[7];
    const float* Win  = (const float*)d_in[8];
    const float* bin_ = (const float*)d_in[9];
    const float* Wout = (const float*)d_in[10];
    const float* bout = (const float*)d_in[11];
    const float* Wfc  = (const float*)d_in[12];
    const float* bfc  = (const float*)d_in[13];
    const float* gamma= (const float*)d_in[14];
    const float* beta = (const float*)d_in[15];
    const int*   req  = (const int*)d_in[16];
    float* out = (float*)d_out;

    uint32_t *dWeffh, *dWcombh, *dmodh, *dctxh;
    float *dbeff, *dbcomb, *dqkv, *dy;
    cudaGetSymbolAddress((void**)&dWeffh,  g_Weffh);
    cudaGetSymbolAddress((void**)&dWcombh, g_Wcombh);
    cudaGetSymbolAddress((void**)&dmodh,   g_modh);
    cudaGetSymbolAddress((void**)&dctxh,   g_ctxh);
    cudaGetSymbolAddress((void**)&dbeff,   g_beff);
    cudaGetSymbolAddress((void**)&dbcomb,  g_bcomb);
    cudaGetSymbolAddress((void**)&dqkv,    g_qkv);
    cudaGetSymbolAddress((void**)&dy,      g_y);

    static int smem_set = 0;
    if (!smem_set) {
        cudaFuncSetAttribute(gemm_h, cudaFuncAttributeMaxDynamicSharedMemorySize, GEMM_SMEM);
        smem_set = 1;
    }

    // 1. fold weights (bf16 out) + biases; convert mod -> bf16x2
    prep_gemmAB<<<dim3(4, 4, 5), 256>>>(Win, Wq, Wk, Wv, Wfc, Wout,
                                        bin_, bq, bk, bv, bout, bfc);
    cvt_bf16_kernel<<<(MROWS*ND/4)/256, 256>>>(mod, dmodh);

    // 2. fused qkv projection: [8192,256] @ [768,256]^T   (bf16 m16n8k16)
    gemm_h<<<dim3(LDQKV / 128, MROWS / 128), 256, GEMM_SMEM>>>(dmodh, dWeffh, dbeff, nullptr, dqkv, LDQKV, KH);

    // 3. banded attention (tf32 tensor cores, R5-proven; ctx out bf16)
    attn_mma<<<dim3(SQ / 64, NB * NH), 128>>>(req, dctxh);

    // 4. fused out_proj+fc with residual: ctx @ (Wfc@Wout)^T + bcomb + mod  (bf16)
    gemm_h<<<dim3(ND / 128, MROWS / 128), 256, GEMM_SMEM>>>(dctxh, dWcombh, dbcomb, mod, dy, ND, KH);

    // 5. layernorm
    ln_kernel<<<MROWS / 8, 256>>>(gamma, beta, out);
}

// round 16
// speedup vs baseline: 1.2926x; 1.0680x over previous
#include <cuda_runtime.h>
#include <math_constants.h>
#include <cstdint>

#define SQ 2048
#define NB 4
#define ND 256
#define NE 256
#define NH 8
#define HD 32
#define MROWS (SQ*NB)       // 8192
#define KH 128              // 256 dims packed as bf16x2
#define QKVW 384            // 768 qkv cols packed as bf16x2

// ---------------- scratch (device globals; no allocation) ----------------
__device__ __align__(16) uint32_t g_Weffh[3*NE*KH];    // bf16x2 (Win_t@Wt), q-scaled
__device__ __align__(16) uint32_t g_Wcombh[ND*KH];     // bf16x2 (Wfc@Wout)
__device__ __align__(16) uint32_t g_modh[(size_t)MROWS*KH];
__device__ __align__(16) uint32_t g_ctxh[(size_t)MROWS*KH];
__device__ __align__(16) uint32_t g_qkvh[(size_t)MROWS*QKVW];
__device__ __align__(16) float g_beff[3*NE];
__device__ __align__(16) float g_bcomb[ND];
__device__ __align__(16) float g_y[(size_t)MROWS*ND];

extern __shared__ float sdyn[];

#define QSCALE 0.17677669529663687f

// ---------------- helpers ----------------
__device__ __forceinline__ void mma_bf16(float c[4],
                                         uint32_t a0, uint32_t a1, uint32_t a2, uint32_t a3,
                                         uint32_t b0, uint32_t b1)
{
    asm volatile("mma.sync.aligned.m16n8k16.row.col.f32.bf16.bf16.f32 "
                 "{%0,%1,%2,%3}, {%4,%5,%6,%7}, {%8,%9}, {%0,%1,%2,%3};"
                 : "+f"(c[0]), "+f"(c[1]), "+f"(c[2]), "+f"(c[3])
                 : "r"(a0), "r"(a1), "r"(a2), "r"(a3), "r"(b0), "r"(b1));
}

__device__ __forceinline__ uint32_t pack_bf16(float lo, float hi) {
    uint32_t r;
    asm("cvt.rn.bf16x2.f32 %0, %1, %2;" : "=r"(r) : "f"(hi), "f"(lo));
    return r;
}

__device__ __forceinline__ void cp16(void* smem_dst, const void* gmem_src) {
    uint32_t sa = (uint32_t)__cvta_generic_to_shared(smem_dst);
    asm volatile("cp.async.cg.shared.global [%0], [%1], 16;\n" :: "r"(sa), "l"(gmem_src));
}

// ---------------- fp32 -> packed bf16x2 (mod) ----------------
__global__ void cvt_bf16_kernel(const float* __restrict__ in, uint32_t* __restrict__ out)
{
    int i = blockIdx.x * 256 + threadIdx.x;
    float4 v = *(const float4*)&in[(size_t)i * 4];
    out[(size_t)i*2 + 0] = pack_bf16(v.x, v.y);
    out[(size_t)i*2 + 1] = pack_bf16(v.z, v.w);
}

// ---------------- prep: 4 small 256^3 products (bf16 out, q scaled) + bias folds ----------------
__global__ void prep_gemmAB(const float* __restrict__ Win,
                            const float* __restrict__ Wq, const float* __restrict__ Wk,
                            const float* __restrict__ Wv, const float* __restrict__ Wfc,
                            const float* __restrict__ Wout,
                            const float* __restrict__ bin_, const float* __restrict__ bq,
                            const float* __restrict__ bk, const float* __restrict__ bv,
                            const float* __restrict__ bout, const float* __restrict__ bfc)
{
    const int t = threadIdx.x;
    if (blockIdx.z == 4) {
        int xb = blockIdx.y * 4 + blockIdx.x;
        int warp = t >> 5, lane = t & 31;
        #pragma unroll
        for (int o = 0; o < 8; o++) {
            int wid = xb * 64 + warp * 8 + o;
            const float* row; const float* vec; float base;
            if (wid < 3*NE) {
                int tt = wid >> 8;
                row = Win + (size_t)wid * NE;
                vec = (tt == 0) ? bq : (tt == 1) ? bk : bv;
                base = bin_[wid];
            } else {
                int r = wid - 3*NE;
                row = Wfc + (size_t)r * NE;
                vec = bout;
                base = bfc[r];
            }
            float s = 0.f;
            #pragma unroll
            for (int u = 0; u < 8; u++) s += row[u*32 + lane] * vec[u*32 + lane];
            #pragma unroll
            for (int off = 16; off >= 1; off >>= 1) s += __shfl_xor_sync(0xffffffffu, s, off);
            if (lane == 0) {
                float v = base + s;
                if (wid < NE)        g_beff[wid] = v * QSCALE;   // q bias scaled
                else if (wid < 3*NE) g_beff[wid] = v;
                else                 g_bcomb[wid - 3*NE] = v;
            }
        }
        return;
    }

    __shared__ __align__(16) float As[16][68];
    __shared__ __align__(16) float Bs[16][68];
    const int tt = blockIdx.z;
    const float* A; const float* B; uint32_t* Ch;
    if (tt < 3) { A = Win + (size_t)tt*NE*NE; B = (tt==0)?Wq:(tt==1)?Wk:Wv; Ch = g_Weffh + (size_t)tt*NE*KH; }
    else        { A = Wfc; B = Wout; Ch = g_Wcombh; }
    const float oscale = (tt == 0) ? QSCALE : 1.f;

    const int m0  = blockIdx.y * 64;
    const int d0  = blockIdx.x * 64;
    const int lrow = t >> 2;
    const int lc4  = (t & 3) << 2;
    const int brow = t >> 4;
    const int bc4  = (t & 15) << 2;
    const int ty = t >> 4, tx = t & 15;

    float acc[4][4] = {};
    for (int k0 = 0; k0 < NE; k0 += 16) {
        float4 av = *(const float4*)&A[(size_t)(m0 + lrow)*NE + k0 + lc4];
        As[lc4+0][lrow] = av.x; As[lc4+1][lrow] = av.y;
        As[lc4+2][lrow] = av.z; As[lc4+3][lrow] = av.w;
        *(float4*)&Bs[brow][bc4] = *(const float4*)&B[(size_t)(k0 + brow)*NE + d0 + bc4];
        __syncthreads();
        #pragma unroll
        for (int kk = 0; kk < 16; kk++) {
            float4 a4 = *(const float4*)&As[kk][ty << 2];
            float4 b4 = *(const float4*)&Bs[kk][tx << 2];
            float ar[4] = {a4.x, a4.y, a4.z, a4.w};
            float br[4] = {b4.x, b4.y, b4.z, b4.w};
            #pragma unroll
            for (int i = 0; i < 4; i++)
                #pragma unroll
                for (int j = 0; j < 4; j++)
                    acc[i][j] += ar[i] * br[j];
        }
        __syncthreads();
    }
    #pragma unroll
    for (int i = 0; i < 4; i++) {
        uint32_t u0 = pack_bf16(acc[i][0]*oscale, acc[i][1]*oscale);
        uint32_t u1 = pack_bf16(acc[i][2]*oscale, acc[i][3]*oscale);
        *(uint2*)&Ch[(size_t)(m0 + (ty<<2) + i)*KH + ((d0 + (tx<<2)) >> 1)] = make_uint2(u0, u1);
    }
}

// ---------------- bf16 tensor-core GEMM: 128x128, BK=32, 2-stage dist-1 ----------------
// A,W packed bf16x2 [.][K2] uint32. If Cpack != null: write packed bf16x2 (no resid).
// Else write fp32 C (+bias, +resid).
#define ST2 20
#define HSTAGE (128*ST2)
#define GEMM_SMEM (4*HSTAGE*(int)sizeof(uint32_t))   // 40960 B
__global__ void __launch_bounds__(256) gemm_h(const uint32_t* __restrict__ A,
                                              const uint32_t* __restrict__ W,
                                              const float* __restrict__ bias,
                                              const float* __restrict__ resid,
                                              float* __restrict__ C,
                                              uint32_t* __restrict__ Cpack,
                                              int N, int K2)
{
    uint32_t* AsB = (uint32_t*)sdyn;
    uint32_t* BsB = AsB + 2*HSTAGE;
    const int tid = threadIdx.x;
    const int m0 = blockIdx.y * 128;
    const int n0 = blockIdx.x * 128;
    const int warp = tid >> 5;
    const int lane = tid & 31;
    const int wm = warp >> 2;
    const int wn = warp & 3;
    const int grp = lane >> 2;
    const int tig = lane & 3;
    const int ldr = tid >> 2;
    const int ldc2 = (tid & 3) << 2;

    const int T = K2 >> 4;
    float acc[4][4][4] = {};

    {
        uint32_t* As = AsB; uint32_t* Bs = BsB;
        #pragma unroll
        for (int p = 0; p < 2; p++) {
            int row = ldr + p * 64;
            cp16(&As[row*ST2 + ldc2], &A[(size_t)(m0 + row)*K2 + ldc2]);
            cp16(&Bs[row*ST2 + ldc2], &W[(size_t)(n0 + row)*K2 + ldc2]);
        }
        asm volatile("cp.async.commit_group;\n");
    }

    for (int t = 0; t < T; t++) {
        if (t + 1 < T) {
            int buf = (t + 1) & 1;
            int k2 = (t + 1) << 4;
            uint32_t* As = AsB + buf*HSTAGE;
            uint32_t* Bs = BsB + buf*HSTAGE;
            #pragma unroll
            for (int p = 0; p < 2; p++) {
                int row = ldr + p * 64;
                cp16(&As[row*ST2 + ldc2], &A[(size_t)(m0 + row)*K2 + k2 + ldc2]);
                cp16(&Bs[row*ST2 + ldc2], &W[(size_t)(n0 + row)*K2 + k2 + ldc2]);
            }
            asm volatile("cp.async.commit_group;\n");
            asm volatile("cp.async.wait_group 1;\n");
        } else {
            asm volatile("cp.async.wait_group 0;\n");
        }
        __syncthreads();

        const uint32_t* As = AsB + (t & 1)*HSTAGE;
        const uint32_t* Bs = BsB + (t & 1)*HSTAGE;
        #pragma unroll
        for (int kp = 0; kp < 16; kp += 8) {
            uint32_t af[4][4], bf[4][2];
            #pragma unroll
            for (int mt = 0; mt < 4; mt++) {
                int r = (wm*64 + mt*16 + grp) * ST2;
                af[mt][0] = As[r + kp + tig];
                af[mt][1] = As[r + 8*ST2 + kp + tig];
                af[mt][2] = As[r + kp + 4 + tig];
                af[mt][3] = As[r + 8*ST2 + kp + 4 + tig];
            }
            #pragma unroll
            for (int nt = 0; nt < 4; nt++) {
                int c = (wn*32 + nt*8 + grp) * ST2;
                bf[nt][0] = Bs[c + kp + tig];
                bf[nt][1] = Bs[c + kp + 4 + tig];
            }
            #pragma unroll
            for (int mt = 0; mt < 4; mt++)
                #pragma unroll
                for (int nt = 0; nt < 4; nt++)
                    mma_bf16(acc[mt][nt], af[mt][0], af[mt][1], af[mt][2], af[mt][3],
                             bf[nt][0], bf[nt][1]);
        }
        __syncthreads();
    }

    const int N2 = N >> 1;
    #pragma unroll
    for (int mt = 0; mt < 4; mt++) {
        #pragma unroll
        for (int nt = 0; nt < 4; nt++) {
            int col = n0 + wn*32 + nt*8 + 2*tig;
            float bx = bias[col], by = bias[col + 1];
            int r0 = m0 + wm*64 + mt*16 + grp;
            float2 o0 = {acc[mt][nt][0] + bx, acc[mt][nt][1] + by};
            float2 o1 = {acc[mt][nt][2] + bx, acc[mt][nt][3] + by};
            if (Cpack) {
                Cpack[(size_t)r0 * N2 + (col >> 1)]       = pack_bf16(o0.x, o0.y);
                Cpack[(size_t)(r0 + 8) * N2 + (col >> 1)] = pack_bf16(o1.x, o1.y);
            } else {
                if (resid) {
                    float2 r0v = *(const float2*)&resid[(size_t)r0 * N + col];
                    float2 r1v = *(const float2*)&resid[(size_t)(r0 + 8) * N + col];
                    o0.x += r0v.x; o0.y += r0v.y;
                    o1.x += r1v.x; o1.y += r1v.y;
                }
                *(float2*)&C[(size_t)r0 * N + col] = o0;
                *(float2*)&C[(size_t)(r0 + 8) * N + col] = o1;
            }
        }
    }
}

// ---------------- banded attention, full bf16 tensor cores ----------------
// Block: 64 queries x one (b,h), 128 threads (4 warps), warp owns 16 queries.
// S[16x64] = Q @ K^T (bf16 k16), masked softmax in regs, C[16x32] = P @ V (bf16).
#define AQST 20    // sQ u32 row stride
#define AKST 20    // sK u32 row stride
#define AVST 60    // sVT u32 row stride (120 bf16 keys)
#define APST 36    // sP u32 row stride
#define AKROWS 112
__global__ void __launch_bounds__(128) attn_mma(const int* __restrict__ reqp,
                                                uint32_t* __restrict__ ctxh)
{
    __shared__ uint32_t sK[AKROWS*AKST];     // 2240 u32
    __shared__ uint32_t sVT[32*AVST];        // 1920 u32 (bf16 [dim][key])
    __shared__ uint32_t sU[4*16*APST];       // 2304 u32: union sQ(64x20=1280) / sP

    const uint32_t* qkvh = g_qkvh;
    const int req = *reqp;
    const int bh = blockIdx.y;
    const int b = bh >> 3;
    const int hoff2 = (bh & 7) * (HD/2);     // u32 offset of head
    const int q0 = blockIdx.x * 64;
    const int wbase = q0 - (req - 1);

    const int tid = threadIdx.x;
    const int w = tid >> 5;
    const int lane = tid & 31;
    const int grp = lane >> 2;
    const int tig = lane & 3;
    uint16_t* sVTb = (uint16_t*)sVT;

    // ---- stage Q (already scaled), K, V^T ----
    #pragma unroll
    for (int u = tid; u < 64*4; u += 128) {          // Q: 64 rows x 4 uint4
        int r = u >> 2, c4 = (u & 3) << 2;
        uint4 v = *(const uint4*)&qkvh[(size_t)((q0 + r)*NB + b)*QKVW + hoff2 + c4];
        *(uint4*)&sU[r*AQST + c4] = v;
    }
    #pragma unroll
    for (int u = tid; u < AKROWS*4; u += 128) {      // K + V: 112 rows x 4 uint4
        int r = u >> 2, c4 = (u & 3) << 2;
        int key = wbase + r;
        uint4 kv = {0,0,0,0}, vv = {0,0,0,0};
        if (key >= 0 && key < SQ) {
            size_t base = (size_t)(key*NB + b)*QKVW + hoff2;
            kv = *(const uint4*)&qkvh[base + 128 + c4];
            vv = *(const uint4*)&qkvh[base + 256 + c4];
        }
        *(uint4*)&sK[r*AKST + c4] = kv;
        uint32_t vw[4] = {vv.x, vv.y, vv.z, vv.w};
        #pragma unroll
        for (int j = 0; j < 4; j++) {
            int d = 2*(c4 + j);
            sVTb[d*120 + r]       = (uint16_t)(vw[j] & 0xffffu);
            sVTb[(d+1)*120 + r]   = (uint16_t)(vw[j] >> 16);
        }
    }
    __syncthreads();

    // ---- scores: S[16x64] = Q @ K^T (2 k16 MMAs per nt) ----
    float sc[8][4] = {};
    #pragma unroll
    for (int kp = 0; kp < 16; kp += 8) {
        uint32_t af[4], bf[8][2];
        {
            int rq = (w*16 + grp) * AQST;
            af[0] = sU[rq + kp + tig];
            af[1] = sU[rq + 8*AQST + kp + tig];
            af[2] = sU[rq + kp + 4 + tig];
            af[3] = sU[rq + 8*AQST + kp + 4 + tig];
        }
        #pragma unroll
        for (int nt = 0; nt < 8; nt++) {
            int rk = (w*16 + nt*8 + grp) * AKST;
            bf[nt][0] = sK[rk + kp + tig];
            bf[nt][1] = sK[rk + kp + 4 + tig];
        }
        #pragma unroll
        for (int nt = 0; nt < 8; nt++)
            mma_bf16(sc[nt], af[0], af[1], af[2], af[3], bf[nt][0], bf[nt][1]);
    }

    // ---- mask + softmax (registers) ----
    const int iw = q0 + w*16;
    const int jw = wbase + w*16;
    float mx0 = -CUDART_INF_F, mx1 = -CUDART_INF_F;
    {
        int i0 = iw + grp, i1 = i0 + 8;
        #pragma unroll
        for (int nt = 0; nt < 8; nt++) {
            int j0 = jw + nt*8 + 2*tig;
            int j1 = j0 + 1;
            bool g0 = (j0 >= 0) & (j0 < SQ);
            bool g1 = (j1 >= 0) & (j1 < SQ);
            float* c = sc[nt];
            c[0] = (g0 && abs(i0 - j0) < req) ? c[0] : -CUDART_INF_F;
            c[1] = (g1 && abs(i0 - j1) < req) ? c[1] : -CUDART_INF_F;
            c[2] = (g0 && abs(i1 - j0) < req) ? c[2] : -CUDART_INF_F;
            c[3] = (g1 && abs(i1 - j1) < req) ? c[3] : -CUDART_INF_F;
            mx0 = fmaxf(mx0, fmaxf(c[0], c[1]));
            mx1 = fmaxf(mx1, fmaxf(c[2], c[3]));
        }
    }
    #pragma unroll
    for (int o = 1; o <= 2; o <<= 1) {
        mx0 = fmaxf(mx0, __shfl_xor_sync(0xffffffffu, mx0, o));
        mx1 = fmaxf(mx1, __shfl_xor_sync(0xffffffffu, mx1, o));
    }
    float s0 = 0.f, s1 = 0.f;
    #pragma unroll
    for (int nt = 0; nt < 8; nt++) {
        float* c = sc[nt];
        c[0] = __expf(c[0] - mx0);
        c[1] = __expf(c[1] - mx0);
        c[2] = __expf(c[2] - mx1);
        c[3] = __expf(c[3] - mx1);
        s0 += c[0] + c[1];
        s1 += c[2] + c[3];
    }
    #pragma unroll
    for (int o = 1; o <= 2; o <<= 1) {
        s0 += __shfl_xor_sync(0xffffffffu, s0, o);
        s1 += __shfl_xor_sync(0xffffffffu, s1, o);
    }
    float rs0 = 1.f / s0, rs1 = 1.f / s1;

    // ---- store P packed bf16x2 into union region (overwrites Q) ----
    __syncthreads();
    uint32_t* sP = sU + w * (16*APST);
    #pragma unroll
    for (int nt = 0; nt < 8; nt++) {
        float* c = sc[nt];
        sP[grp*APST + nt*4 + tig]       = pack_bf16(c[0], c[1]);
        sP[(grp+8)*APST + nt*4 + tig]   = pack_bf16(c[2], c[3]);
    }
    __syncwarp();

    // ---- ctx: C[16x32] = P[16x64] @ V[64x32] (4 k16 MMAs) ----
    float ao[4][4] = {};
    #pragma unroll
    for (int kp = 0; kp < 32; kp += 8) {
        uint32_t af[4], bf[4][2];
        af[0] = sP[grp*APST + kp + tig];
        af[1] = sP[(grp+8)*APST + kp + tig];
        af[2] = sP[grp*APST + kp + 4 + tig];
        af[3] = sP[(grp+8)*APST + kp + 4 + tig];
        #pragma unroll
        for (int nt = 0; nt < 4; nt++) {
            int rv = (nt*8 + grp) * AVST + w*8;
            bf[nt][0] = sVT[rv + kp + tig];
            bf[nt][1] = sVT[rv + kp + 4 + tig];
        }
        #pragma unroll
        for (int nt = 0; nt < 4; nt++)
            mma_bf16(ao[nt], af[0], af[1], af[2], af[3], bf[nt][0], bf[nt][1]);
    }

    // ---- epilogue: divide by row sums, write ctx packed bf16x2 ----
    {
        int i0 = iw + grp;
        int hb = (bh & 7) * (HD/2);
        #pragma unroll
        for (int nt = 0; nt < 4; nt++) {
            int dc2 = hb + ((nt*8 + 2*tig) >> 1);
            ctxh[(size_t)(i0*NB + b)*KH + dc2] =
                pack_bf16(ao[nt][0] * rs0, ao[nt][1] * rs0);
            ctxh[(size_t)((i0 + 8)*NB + b)*KH + dc2] =
                pack_bf16(ao[nt][2] * rs1, ao[nt][3] * rs1);
        }
    }
}

// ---------------- layernorm (warp per row of 256, float4) ----------------
__global__ void ln_kernel(const float* __restrict__ gamma, const float* __restrict__ beta,
                          float* __restrict__ out)
{
    int row = blockIdx.x * 8 + (threadIdx.x >> 5);
    int lane = threadIdx.x & 31;
    const float* yr = g_y + (size_t)row * ND;
    float4 a = *(const float4*)&yr[lane * 4];
    float4 c = *(const float4*)&yr[128 + lane * 4];
    float s  = a.x + a.y + a.z + a.w + c.x + c.y + c.z + c.w;
    float s2 = a.x*a.x + a.y*a.y + a.z*a.z + a.w*a.w
             + c.x*c.x + c.y*c.y + c.z*c.z + c.w*c.w;
    #pragma unroll
    for (int o = 16; o >= 1; o >>= 1) {
        s  += __shfl_xor_sync(0xffffffffu, s, o);
        s2 += __shfl_xor_sync(0xffffffffu, s2, o);
    }
    float mu  = s * (1.f / ND);
    float var = s2 * (1.f / ND) - mu * mu;
    float inv = rsqrtf(var + 1e-6f);
    float4 g0 = *(const float4*)&gamma[lane * 4];
    float4 g1 = *(const float4*)&gamma[128 + lane * 4];
    float4 b0 = *(const float4*)&beta[lane * 4];
    float4 b1 = *(const float4*)&beta[128 + lane * 4];
    float4 o0 = {(a.x - mu)*inv*g0.x + b0.x, (a.y - mu)*inv*g0.y + b0.y,
                 (a.z - mu)*inv*g0.z + b0.z, (a.w - mu)*inv*g0.w + b0.w};
    float4 o1 = {(c.x - mu)*inv*g1.x + b1.x, (c.y - mu)*inv*g1.y + b1.y,
                 (c.z - mu)*inv*g1.z + b1.z, (c.w - mu)*inv*g1.w + b1.w};
    *(float4*)&out[(size_t)row * ND + lane * 4] = o0;
    *(float4*)&out[(size_t)row * ND + 128 + lane * 4] = o1;
}

// ---------------- launch ----------------
extern "C" void kernel_launch(void* const* d_in, const int* in_sizes, int n_in,
                              void* d_out, int out_size)
{
    const float* mod  = (const float*)d_in[0];
    const float* Wq   = (const float*)d_in[2];
    const float* bq   = (const float*)d_in[3];
    const float* Wk   = (const float*)d_in[4];
    const float* bk   = (const float*)d_in[5];
    const float* Wv   = (const float*)d_in[6];
    const float* bv   = (const float*)d_in[7];
    const float* Win  = (const float*)d_in[8];
    const float* bin_ = (const float*)d_in[9];
    const float* Wout = (const float*)d_in[10];
    const float* bout = (const float*)d_in[11];
    const float* Wfc  = (const float*)d_in[12];
    const float* bfc  = (const float*)d_in[13];
    const float* gamma= (const float*)d_in[14];
    const float* beta = (const float*)d_in[15];
    const int*   req  = (const int*)d_in[16];
    float* out = (float*)d_out;

    uint32_t *dWeffh, *dWcombh, *dmodh, *dctxh, *dqkvh;
    float *dbeff, *dbcomb, *dy;
    cudaGetSymbolAddress((void**)&dWeffh,  g_Weffh);
    cudaGetSymbolAddress((void**)&dWcombh, g_Wcombh);
    cudaGetSymbolAddress((void**)&dmodh,   g_modh);
    cudaGetSymbolAddress((void**)&dctxh,   g_ctxh);
    cudaGetSymbolAddress((void**)&dqkvh,   g_qkvh);
    cudaGetSymbolAddress((void**)&dbeff,   g_beff);
    cudaGetSymbolAddress((void**)&dbcomb,  g_bcomb);
    cudaGetSymbolAddress((void**)&dy,      g_y);

    static int smem_set = 0;
    if (!smem_set) {
        cudaFuncSetAttribute(gemm_h, cudaFuncAttributeMaxDynamicSharedMemorySize, GEMM_SMEM);
        smem_set = 1;
    }

    // 1. fold weights (bf16, q pre-scaled) + biases; convert mod -> bf16x2
    prep_gemmAB<<<dim3(4, 4, 5), 256>>>(Win, Wq, Wk, Wv, Wfc, Wout,
                                        bin_, bq, bk, bv, bout, bfc);
    cvt_bf16_kernel<<<(MROWS*ND/4)/256, 256>>>(mod, dmodh);

    // 2. fused qkv projection -> packed bf16x2 qkv
    gemm_h<<<dim3(768 / 128, MROWS / 128), 256, GEMM_SMEM>>>(
        dmodh, dWeffh, dbeff, nullptr, nullptr, dqkvh, 768, KH);

    // 3. banded attention (full bf16 tensor cores)
    attn_mma<<<dim3(SQ / 64, NB * NH), 128>>>(req, dctxh);

    // 4. fused out_proj+fc with residual (fp32 out)
    gemm_h<<<dim3(ND / 128, MROWS / 128), 256, GEMM_SMEM>>>(
        dctxh, dWcombh, dbcomb, mod, dy, nullptr, ND, KH);

    // 5. layernorm
    ln_kernel<<<MROWS / 8, 256>>>(gamma, beta, out);
}